// round 11
// baseline (speedup 1.0000x reference)
#include <cuda_runtime.h>
#include <cuda_bf16.h>
#include <cstdint>
#include <cstddef>

#define QLEN 1024
#define BSZ 4
#define DM 1024
#define NH 16
#define DH 64
#define BN_TOT 64
#define NEGINF -1e30f
#define KDIM 1024

__device__ __forceinline__ uint32_t smem_to_u32(const void* p) {
    uint32_t a;
    asm("{ .reg .u64 t; cvta.to.shared.u64 t, %1; cvt.u32.u64 %0, t; }" : "=r"(a) : "l"(p));
    return a;
}
#define SWZ128(b) ((b) ^ (((b) >> 3) & 0x70))

__device__ __forceinline__ void ldm_x4(uint32_t r[4], uint32_t addr) {
    asm volatile("ldmatrix.sync.aligned.m8n8.x4.shared.b16 {%0,%1,%2,%3}, [%4];"
                 : "=r"(r[0]), "=r"(r[1]), "=r"(r[2]), "=r"(r[3]) : "r"(addr));
}
__device__ __forceinline__ void mma16816(float c[4], const uint32_t a[4], const uint32_t b[2]) {
    asm volatile("mma.sync.aligned.m16n8k16.row.col.f32.bf16.bf16.f32 "
                 "{%0,%1,%2,%3}, {%4,%5,%6,%7}, {%8,%9}, {%0,%1,%2,%3};"
                 : "+f"(c[0]), "+f"(c[1]), "+f"(c[2]), "+f"(c[3])
                 : "r"(a[0]), "r"(a[1]), "r"(a[2]), "r"(a[3]), "r"(b[0]), "r"(b[1]));
}
__device__ __forceinline__ void cp_async16(uint32_t saddr, const void* gptr) {
    asm volatile("cp.async.cg.shared.global [%0], [%1], 16;" :: "r"(saddr), "l"(gptr));
}
__device__ __forceinline__ void cp_commit() { asm volatile("cp.async.commit_group;"); }
template <int N>
__device__ __forceinline__ void cp_wait() { asm volatile("cp.async.wait_group %0;" :: "n"(N)); }

// ---------------- scratch ----------------
__device__ float g_heads[(size_t)QLEN * BSZ * 3 * DM];
__device__ float g_rk[(size_t)QLEN * DM];
__device__ float g_BD[(size_t)BN_TOT * QLEN * QLEN];
__device__ float g_attn[(size_t)QLEN * BSZ * DM];
__device__ __nv_bfloat16 g_wbf[(size_t)QLEN * BSZ * 2 * KDIM];
__device__ __nv_bfloat16 g_rbf[(size_t)QLEN * 2 * KDIM];
__device__ __nv_bfloat16 g_qkvt[(size_t)3 * DM * 2 * KDIM];
__device__ __nv_bfloat16 g_wrt[(size_t)DM * 2 * KDIM];
__device__ __nv_bfloat16 g_wot[(size_t)DM * 2 * KDIM];
__device__ __nv_bfloat16 g_qwbf[(size_t)BN_TOT * QLEN * 2 * DH];   // pre-scaled by 0.125
__device__ __nv_bfloat16 g_qrbf[(size_t)BN_TOT * QLEN * 2 * DH];   // pre-scaled by 0.125
__device__ __nv_bfloat16 g_kbf[(size_t)BN_TOT * QLEN * 2 * DH];
__device__ __nv_bfloat16 g_rkbf[(size_t)NH * QLEN * 2 * DH];
__device__ __nv_bfloat16 g_vtbf[(size_t)BN_TOT * DH * 2 * QLEN];
__device__ __nv_bfloat16 g_vecbf[(size_t)QLEN * BSZ * 2 * KDIM];

__device__ __forceinline__ void split2(float x, __nv_bfloat16& h, __nv_bfloat16& l) {
    h = __float2bfloat16(x);
    l = __float2bfloat16(x - __bfloat162float(h));
}

// ---------------- HMMA GEMM: load-once 3-pass hi/lo ----------------
// mode 0: full grid; 2: anti-tri 8x8 (BD)
template <int BM, int BN>
__global__ __launch_bounds__(256) void mma_gemm2(
    const __nv_bfloat16* __restrict__ A, const __nv_bfloat16* __restrict__ Bt,
    float* __restrict__ C, int K, int lda, int ldb, int ldc,
    long long sA, long long sB, long long sC, int mode, int bmask)
{
    extern __shared__ char smem[];
    const uint32_t smem_u32 = smem_to_u32(smem);
    constexpr int AHB = BM * 128;
    constexpr int BHB = BN * 128;
    constexpr int STG = 2 * AHB + 2 * BHB;
    constexpr int WN = BN / 2;
    constexpr int MT = 2;
    constexpr int NT = WN / 8;

    const int tid = threadIdx.x;
    const int lane = tid & 31, warp = tid >> 5;
    const int wm = warp & 3, wn = warp >> 2;
    const int bz = blockIdx.z;

    int m0, n0;
    if (mode == 0) {
        m0 = blockIdx.y * BM;
        n0 = blockIdx.x * BN;
    } else {
        int x = blockIdx.x;
        int it = (int)floorf((sqrtf(8.f * x + 1.f) - 1.f) * 0.5f);
        while ((it + 1) * (it + 2) / 2 <= x) ++it;
        while (it * (it + 1) / 2 > x) --it;
        int jt = x - it * (it + 1) / 2;
        m0 = it * BM;
        n0 = (7 - jt) * BN;
    }

    const __nv_bfloat16* Ab = A + (size_t)bz * sA;
    const __nv_bfloat16* Bb = Bt + (size_t)(bz & bmask) * sB;

    const int KT = K / 64;

    auto cp_stage = [&](int kt, int s) {
        const uint32_t base = smem_u32 + s * STG;
#pragma unroll
        for (int i = 0; i < BM / 32; i++) {
            int c = tid + i * 256, row = c >> 3, q = c & 7;
            uint32_t sw = SWZ128(row * 128 + q * 16);
            const __nv_bfloat16* gp = Ab + (size_t)(m0 + row) * lda + kt * 64 + q * 8;
            cp_async16(base + sw, gp);
            cp_async16(base + AHB + sw, gp + K);
        }
#pragma unroll
        for (int i = 0; i < BN / 32; i++) {
            int c = tid + i * 256, row = c >> 3, q = c & 7;
            uint32_t sw = SWZ128(row * 128 + q * 16);
            const __nv_bfloat16* gp = Bb + (size_t)(n0 + row) * ldb + kt * 64 + q * 8;
            cp_async16(base + 2 * AHB + sw, gp);
            cp_async16(base + 2 * AHB + BHB + sw, gp + K);
        }
        cp_commit();
    };

    float acc[MT][NT][4];
#pragma unroll
    for (int mt = 0; mt < MT; mt++)
#pragma unroll
        for (int nt = 0; nt < NT; nt++)
#pragma unroll
            for (int u = 0; u < 4; u++) acc[mt][nt][u] = 0.f;

    cp_stage(0, 0);
    if (KT > 1) cp_stage(1, 1);

    for (int t = 0; t < KT; t++) {
        const int s = t & 1;
        if (t < KT - 1) cp_wait<1>(); else cp_wait<0>();
        __syncthreads();

        const uint32_t ah = smem_u32 + s * STG;
        const uint32_t al = ah + AHB;
        const uint32_t bh = ah + 2 * AHB;
        const uint32_t bl = bh + BHB;
#pragma unroll
        for (int kk = 0; kk < 4; kk++) {
            const int seg = kk * 32 + (lane >> 4) * 16;
            uint32_t afh[MT][4], afl[MT][4], bfh[NT][2], bfl[NT][2];
#pragma unroll
            for (int mt = 0; mt < MT; mt++) {
                int sw = SWZ128((wm * 32 + mt * 16 + (lane & 15)) * 128 + seg);
                ldm_x4(afh[mt], ah + sw);
                ldm_x4(afl[mt], al + sw);
            }
#pragma unroll
            for (int p = 0; p < NT / 2; p++) {
                int sw = SWZ128((wn * WN + p * 16 + (lane & 15)) * 128 + seg);
                uint32_t r[4];
                ldm_x4(r, bh + sw);
                bfh[2 * p][0] = r[0]; bfh[2 * p][1] = r[2];
                bfh[2 * p + 1][0] = r[1]; bfh[2 * p + 1][1] = r[3];
                ldm_x4(r, bl + sw);
                bfl[2 * p][0] = r[0]; bfl[2 * p][1] = r[2];
                bfl[2 * p + 1][0] = r[1]; bfl[2 * p + 1][1] = r[3];
            }
#pragma unroll
            for (int mt = 0; mt < MT; mt++)
#pragma unroll
                for (int nt = 0; nt < NT; nt++)
                    mma16816(acc[mt][nt], afh[mt], bfh[nt]);
#pragma unroll
            for (int mt = 0; mt < MT; mt++)
#pragma unroll
                for (int nt = 0; nt < NT; nt++)
                    mma16816(acc[mt][nt], afl[mt], bfh[nt]);
#pragma unroll
            for (int mt = 0; mt < MT; mt++)
#pragma unroll
                for (int nt = 0; nt < NT; nt++)
                    mma16816(acc[mt][nt], afh[mt], bfl[nt]);
        }
        __syncthreads();
        if (t + 2 < KT) cp_stage(t + 2, s);
    }

    float* Cb = C + (size_t)bz * sC;
#pragma unroll
    for (int mt = 0; mt < MT; mt++)
#pragma unroll
        for (int nt = 0; nt < NT; nt++) {
            int mrow = m0 + wm * 32 + mt * 16 + (lane >> 2);
            int col = n0 + wn * WN + nt * 8 + (lane & 3) * 2;
            *(float2*)&Cb[(size_t)mrow * ldc + col] = make_float2(acc[mt][nt][0], acc[mt][nt][1]);
            *(float2*)&Cb[(size_t)(mrow + 8) * ldc + col] = make_float2(acc[mt][nt][2], acc[mt][nt][3]);
        }
}

// ---------------- flash kernel: AC(HMMA) + shifted BD + no-max softmax + PV ----------------
__global__ __launch_bounds__(256) void flash_kernel()
{
    extern __shared__ char smem[];
    const uint32_t su = smem_to_u32(smem);
    constexpr int OFF_QWH = 0, OFF_QWL = 16384;
    constexpr int OFF_K = 32768;          // two stages of 32768 (hi | lo 16384)
    constexpr int OFF_VH = 98304;         // 2 chunks * 8192
    constexpr int OFF_VL = 114688;
    constexpr int OFF_PH = 131072;        // 2 chunks * 16384
    constexpr int OFF_PL = 163840;
    constexpr int OFF_RC = 196608;        // final l combine (2*128 floats)

    const int tid = threadIdx.x;
    const int lane = tid & 31, warp = tid >> 5;
    const int wm = warp & 3, wn = warp >> 2;
    const int bn = blockIdx.z;
    const int it = 7 - blockIdx.x;        // heavy tiles first
    const int i0 = it * 128;

    const __nv_bfloat16* qw = g_qwbf + (size_t)bn * QLEN * 128;
    const __nv_bfloat16* kb = g_kbf + (size_t)bn * QLEN * 128;
    const __nv_bfloat16* vt = g_vtbf + (size_t)bn * DH * 2048;
    const float* bdb = g_BD + (size_t)bn * QLEN * QLEN;
    float* redC = (float*)(smem + OFF_RC);

    // preload QW hi/lo + K tile 0 (one cp.async group)
#pragma unroll
    for (int i = 0; i < 4; i++) {
        int c = tid + i * 256, row = c >> 3, q = c & 7;
        uint32_t sw = SWZ128(row * 128 + q * 16);
        const __nv_bfloat16* gp = qw + (size_t)(i0 + row) * 128 + q * 8;
        cp_async16(su + OFF_QWH + sw, gp);
        cp_async16(su + OFF_QWL + sw, gp + 64);
    }
#pragma unroll
    for (int i = 0; i < 4; i++) {
        int c = tid + i * 256, row = c >> 3, q = c & 7;
        uint32_t sw = SWZ128(row * 128 + q * 16);
        const __nv_bfloat16* gp = kb + (size_t)row * 128 + q * 8;
        cp_async16(su + OFF_K + sw, gp);
        cp_async16(su + OFF_K + 16384 + sw, gp + 64);
    }
    cp_commit();

    float acc_o[2][4][4];
#pragma unroll
    for (int mt = 0; mt < 2; mt++)
#pragma unroll
        for (int nt = 0; nt < 4; nt++)
#pragma unroll
            for (int u = 0; u < 4; u++) acc_o[mt][nt][u] = 0.f;
    float lsum[4];
#pragma unroll
    for (int i = 0; i < 4; i++) lsum[i] = 0.f;

    for (int jt = 0; jt <= it; jt++) {
        const int s = jt & 1;
        const int j0 = jt * 128;
        const bool more = (jt < it);
        cp_wait<0>();
        __syncthreads();

        // issue V_jt (group), then next K (group)
#pragma unroll
        for (int i = 0; i < 8; i++) {
            int c = tid + i * 256;
            int q = c & 7, row = (c >> 3) & 63, ch = (c >> 9) & 1, hf = c >> 10;
            uint32_t sw = SWZ128(row * 128 + q * 16) + ch * 8192;
            const __nv_bfloat16* gp = vt + (size_t)row * 2048 + hf * 1024 + j0 + ch * 64 + q * 8;
            cp_async16(su + (hf ? OFF_VL : OFF_VH) + sw, gp);
        }
        cp_commit();
        if (more) {
            int j0n = j0 + 128;
#pragma unroll
            for (int i = 0; i < 4; i++) {
                int c = tid + i * 256, row = c >> 3, q = c & 7;
                uint32_t sw = SWZ128(row * 128 + q * 16);
                const __nv_bfloat16* gp = kb + (size_t)(j0n + row) * 128 + q * 8;
                cp_async16(su + OFF_K + (s ^ 1) * 32768 + sw, gp);
                cp_async16(su + OFF_K + (s ^ 1) * 32768 + 16384 + sw, gp + 64);
            }
            cp_commit();
        }

        // ---- S = qw @ k^T (3-term) ----
        float accS[2][8][4];
#pragma unroll
        for (int mt = 0; mt < 2; mt++)
#pragma unroll
            for (int nt = 0; nt < 8; nt++)
#pragma unroll
                for (int u = 0; u < 4; u++) accS[mt][nt][u] = 0.f;

        const uint32_t ah_ = su + OFF_QWH, al_ = su + OFF_QWL;
        const uint32_t bh_ = su + OFF_K + s * 32768, bl_ = bh_ + 16384;
#pragma unroll
        for (int kk = 0; kk < 4; kk++) {
            const int seg = kk * 32 + (lane >> 4) * 16;
            uint32_t afh[2][4], afl[2][4], bfh[8][2], bfl[8][2];
#pragma unroll
            for (int mt = 0; mt < 2; mt++) {
                int sw = SWZ128((wm * 32 + mt * 16 + (lane & 15)) * 128 + seg);
                ldm_x4(afh[mt], ah_ + sw);
                ldm_x4(afl[mt], al_ + sw);
            }
#pragma unroll
            for (int p = 0; p < 4; p++) {
                int sw = SWZ128((wn * 64 + p * 16 + (lane & 15)) * 128 + seg);
                uint32_t r[4];
                ldm_x4(r, bh_ + sw);
                bfh[2 * p][0] = r[0]; bfh[2 * p][1] = r[2];
                bfh[2 * p + 1][0] = r[1]; bfh[2 * p + 1][1] = r[3];
                ldm_x4(r, bl_ + sw);
                bfl[2 * p][0] = r[0]; bfl[2 * p][1] = r[2];
                bfl[2 * p + 1][0] = r[1]; bfl[2 * p + 1][1] = r[3];
            }
#pragma unroll
            for (int mt = 0; mt < 2; mt++)
#pragma unroll
                for (int nt = 0; nt < 8; nt++)
                    mma16816(accS[mt][nt], afh[mt], bfh[nt]);
#pragma unroll
            for (int mt = 0; mt < 2; mt++)
#pragma unroll
                for (int nt = 0; nt < 8; nt++)
                    mma16816(accS[mt][nt], afl[mt], bfh[nt]);
#pragma unroll
            for (int mt = 0; mt < 2; mt++)
#pragma unroll
                for (int nt = 0; nt < 8; nt++)
                    mma16816(accS[mt][nt], afh[mt], bfl[nt]);
        }

        // ---- + shifted BD, causal mask, p = exp(s) (no max: scores bounded) ----
#pragma unroll
        for (int mt = 0; mt < 2; mt++)
#pragma unroll
            for (int hf = 0; hf < 2; hf++) {
                int row_l = wm * 32 + mt * 16 + (lane >> 2) + hf * 8;
                int gi = i0 + row_l;
                const float* bdrow = bdb + (size_t)gi * 1024 + (1023 - gi) + j0;
                int idx = mt * 2 + hf;
                float ssum = 0.f;
#pragma unroll
                for (int nt = 0; nt < 8; nt++)
#pragma unroll
                    for (int e = 0; e < 2; e++) {
                        int col = wn * 64 + nt * 8 + (lane & 3) * 2 + e;
                        int gj = j0 + col;
                        float p = (gj <= gi) ? __expf(accS[mt][nt][hf * 2 + e] + bdrow[col]) : 0.f;
                        accS[mt][nt][hf * 2 + e] = p;
                        ssum += p;
                    }
                lsum[idx] += ssum;
            }

        // ---- store P (split bf16, two 64-col chunks; chunk = wn) ----
#pragma unroll
        for (int mt = 0; mt < 2; mt++)
#pragma unroll
            for (int hf = 0; hf < 2; hf++) {
                int row_l = wm * 32 + mt * 16 + (lane >> 2) + hf * 8;
#pragma unroll
                for (int nt = 0; nt < 8; nt++) {
                    float v0 = accS[mt][nt][hf * 2], v1 = accS[mt][nt][hf * 2 + 1];
                    __nv_bfloat16 h0, l0, h1, l1;
                    split2(v0, h0, l0);
                    split2(v1, h1, l1);
                    uint32_t off = SWZ128(row_l * 128 + (nt * 8 + (lane & 3) * 2) * 2);
                    *(__nv_bfloat162*)(smem + OFF_PH + wn * 16384 + off) = __nv_bfloat162(h0, h1);
                    *(__nv_bfloat162*)(smem + OFF_PL + wn * 16384 + off) = __nv_bfloat162(l0, l1);
                }
            }
        if (more) cp_wait<1>(); else cp_wait<0>();
        __syncthreads();   // P + V visible

        // ---- PV: acc_o += P @ V ----
#pragma unroll
        for (int kk = 0; kk < 8; kk++) {
            const int ch = kk >> 2;
            const int seg = (kk & 3) * 32 + (lane >> 4) * 16;
            uint32_t pah[2][4], pal[2][4], vbh[4][2], vbl[4][2];
#pragma unroll
            for (int mt = 0; mt < 2; mt++) {
                int sw = SWZ128((wm * 32 + mt * 16 + (lane & 15)) * 128 + seg);
                ldm_x4(pah[mt], su + OFF_PH + ch * 16384 + sw);
                ldm_x4(pal[mt], su + OFF_PL + ch * 16384 + sw);
            }
#pragma unroll
            for (int p = 0; p < 2; p++) {
                int sw = SWZ128((wn * 32 + p * 16 + (lane & 15)) * 128 + seg);
                uint32_t r[4];
                ldm_x4(r, su + OFF_VH + ch * 8192 + sw);
                vbh[2 * p][0] = r[0]; vbh[2 * p][1] = r[2];
                vbh[2 * p + 1][0] = r[1]; vbh[2 * p + 1][1] = r[3];
                ldm_x4(r, su + OFF_VL + ch * 8192 + sw);
                vbl[2 * p][0] = r[0]; vbl[2 * p][1] = r[2];
                vbl[2 * p + 1][0] = r[1]; vbl[2 * p + 1][1] = r[3];
            }
#pragma unroll
            for (int mt = 0; mt < 2; mt++)
#pragma unroll
                for (int nt = 0; nt < 4; nt++)
                    mma16816(acc_o[mt][nt], pah[mt], vbh[nt]);
#pragma unroll
            for (int mt = 0; mt < 2; mt++)
#pragma unroll
                for (int nt = 0; nt < 4; nt++)
                    mma16816(acc_o[mt][nt], pal[mt], vbh[nt]);
#pragma unroll
            for (int mt = 0; mt < 2; mt++)
#pragma unroll
                for (int nt = 0; nt < 4; nt++)
                    mma16816(acc_o[mt][nt], pah[mt], vbl[nt]);
        }
        __syncthreads();   // V/P free for next iter
    }

    // ---- combine l across lanes + wn halves (once) ----
#pragma unroll
    for (int idx = 0; idx < 4; idx++) {
        lsum[idx] += __shfl_xor_sync(0xffffffffu, lsum[idx], 1);
        lsum[idx] += __shfl_xor_sync(0xffffffffu, lsum[idx], 2);
    }
    if ((lane & 3) == 0) {
#pragma unroll
        for (int mt = 0; mt < 2; mt++)
#pragma unroll
            for (int hf = 0; hf < 2; hf++) {
                int row_l = wm * 32 + mt * 16 + (lane >> 2) + hf * 8;
                redC[wn * 128 + row_l] = lsum[mt * 2 + hf];
            }
    }
    __syncthreads();

    // ---- epilogue: vec = acc_o / l, split bf16 into g_vecbf ----
    const int b = bn >> 4, n = bn & 15;
#pragma unroll
    for (int mt = 0; mt < 2; mt++)
#pragma unroll
        for (int nt = 0; nt < 4; nt++)
#pragma unroll
            for (int hf = 0; hf < 2; hf++) {
                int row_l = wm * 32 + mt * 16 + (lane >> 2) + hf * 8;
                float inv = 1.f / (redC[row_l] + redC[128 + row_l]);
                int gi = i0 + row_l;
                int d0 = wn * 32 + nt * 8 + (lane & 3) * 2;
                float v0 = acc_o[mt][nt][hf * 2] * inv;
                float v1 = acc_o[mt][nt][hf * 2 + 1] * inv;
                __nv_bfloat16 h0, l0, h1, l1;
                split2(v0, h0, l0);
                split2(v1, h1, l1);
                size_t orow = (size_t)(gi * 4 + b) * 2048 + n * 64 + d0;
                *(__nv_bfloat162*)&g_vecbf[orow] = __nv_bfloat162(h0, h1);
                *(__nv_bfloat162*)&g_vecbf[orow + 1024] = __nv_bfloat162(l0, l1);
            }
}

// ---------------- split / transpose / pack kernels ----------------
__global__ void split_kernel(const float* __restrict__ X, __nv_bfloat16* __restrict__ Y, int cols)
{
    int idx = blockIdx.x * 256 + threadIdx.x;
    int row = idx / cols, col = idx - row * cols;
    __nv_bfloat16 h, l;
    split2(X[idx], h, l);
    Y[(size_t)row * 2 * cols + col] = h;
    Y[(size_t)row * 2 * cols + cols + col] = l;
}

__global__ __launch_bounds__(256) void tsplit_kernel(const float* __restrict__ X,
                                                     __nv_bfloat16* __restrict__ Y, int N, int K)
{
    __shared__ float sm[64][65];
    int k0 = blockIdx.x * 64, n0 = blockIdx.y * 64;
    int tid = threadIdx.x;
    for (int e = tid; e < 4096; e += 256) {
        int r = e >> 6, c = e & 63;
        sm[c][r] = X[(size_t)(k0 + r) * N + n0 + c];
    }
    __syncthreads();
    for (int e = tid; e < 4096; e += 256) {
        int r = e >> 6, c = e & 63;
        __nv_bfloat16 h, l;
        split2(sm[r][c], h, l);
        Y[(size_t)(n0 + r) * 2 * K + k0 + c] = h;
        Y[(size_t)(n0 + r) * 2 * K + K + k0 + c] = l;
    }
}

__global__ void pack_qk_kernel(const float* __restrict__ rwb, const float* __restrict__ rrb)
{
    int idx = blockIdx.x * 256 + threadIdx.x;
    int d = idx & 63, i = (idx >> 6) & 1023, bn = idx >> 16;
    int b = bn >> 4, n = bn & 15;
    size_t hbase = (size_t)(i * 4 + b) * 3072 + n * 64 + d;
    float q = g_heads[hbase];
    float k = g_heads[hbase + 1024];
    size_t o = ((size_t)bn * QLEN + i) * 128 + d;
    __nv_bfloat16 h, l;
    split2((q + rwb[n * 64 + d]) * 0.125f, h, l);
    g_qwbf[o] = h; g_qwbf[o + 64] = l;
    split2((q + rrb[n * 64 + d]) * 0.125f, h, l);
    g_qrbf[o] = h; g_qrbf[o + 64] = l;
    split2(k, h, l);
    g_kbf[o] = h; g_kbf[o + 64] = l;
}

__global__ void pack_rk_kernel()
{
    int idx = blockIdx.x * 256 + threadIdx.x;
    int d = idx & 63, m = (idx >> 6) & 1023, n = idx >> 16;
    __nv_bfloat16 h, l;
    split2(g_rk[(size_t)m * 1024 + n * 64 + d], h, l);
    size_t o = ((size_t)n * QLEN + m) * 128 + d;
    g_rkbf[o] = h; g_rkbf[o + 64] = l;
}

__global__ __launch_bounds__(256) void pack_vt_kernel()
{
    __shared__ float sm[64][65];
    int bn = blockIdx.y, b = bn >> 4, n = bn & 15;
    int j0 = blockIdx.x * 64;
    int tid = threadIdx.x;
    for (int e = tid; e < 4096; e += 256) {
        int jj = e >> 6, d = e & 63;
        sm[d][jj] = g_heads[(size_t)((j0 + jj) * 4 + b) * 3072 + 2048 + n * 64 + d];
    }
    __syncthreads();
    for (int e = tid; e < 4096; e += 256) {
        int d = e >> 6, jj = e & 63;
        __nv_bfloat16 h, l;
        split2(sm[d][jj], h, l);
        g_vtbf[((size_t)bn * 64 + d) * 2048 + j0 + jj] = h;
        g_vtbf[((size_t)bn * 64 + d) * 2048 + 1024 + j0 + jj] = l;
    }
}

// ---------------- residual + layernorm ----------------
__global__ __launch_bounds__(256) void ln_kernel(
    const float* __restrict__ w, const float* __restrict__ gamma,
    const float* __restrict__ beta, float* __restrict__ out)
{
    int row = blockIdx.x;
    const float* wr = w + (size_t)row * DM;
    const float* ar = g_attn + (size_t)row * DM;
    int tid = threadIdx.x;

    float x[4];
    float s = 0.f, s2 = 0.f;
#pragma unroll
    for (int u = 0; u < 4; u++) {
        int c = tid + u * 256;
        x[u] = wr[c] + ar[c];
        s += x[u];
        s2 += x[u] * x[u];
    }
    __shared__ float rs[256], rs2[256];
    rs[tid] = s; rs2[tid] = s2;
    __syncthreads();
    for (int t = 128; t > 0; t >>= 1) {
        if (tid < t) { rs[tid] += rs[tid + t]; rs2[tid] += rs2[tid + t]; }
        __syncthreads();
    }
    float mu = rs[0] * (1.f / DM);
    float var = rs2[0] * (1.f / DM) - mu * mu;
    float rstd = rsqrtf(var + 1e-5f);
#pragma unroll
    for (int u = 0; u < 4; u++) {
        int c = tid + u * 256;
        out[(size_t)row * DM + c] = (x[u] - mu) * rstd * gamma[c] + beta[c];
    }
}

// ---------------- launch ----------------
extern "C" void kernel_launch(void* const* d_in, const int* in_sizes, int n_in,
                              void* d_out, int out_size)
{
    const float* w     = (const float*)d_in[0];
    const float* r     = (const float*)d_in[1];
    const float* rwb   = (const float*)d_in[2];
    const float* rrb   = (const float*)d_in[3];
    const float* W_qkv = (const float*)d_in[5];
    const float* W_r   = (const float*)d_in[6];
    const float* W_o   = (const float*)d_in[7];
    const float* gamma = (const float*)d_in[8];
    const float* beta  = (const float*)d_in[9];
    float* out = (float*)d_out;

    float *p_heads, *p_rk, *p_BD, *p_attn;
    __nv_bfloat16 *p_wbf, *p_rbf, *p_qkvt, *p_wrt, *p_wot;
    __nv_bfloat16 *p_qwbf, *p_qrbf, *p_kbf, *p_rkbf, *p_vtbf, *p_vecbf;
    cudaGetSymbolAddress((void**)&p_heads, g_heads);
    cudaGetSymbolAddress((void**)&p_rk, g_rk);
    cudaGetSymbolAddress((void**)&p_BD, g_BD);
    cudaGetSymbolAddress((void**)&p_attn, g_attn);
    cudaGetSymbolAddress((void**)&p_wbf, g_wbf);
    cudaGetSymbolAddress((void**)&p_rbf, g_rbf);
    cudaGetSymbolAddress((void**)&p_qkvt, g_qkvt);
    cudaGetSymbolAddress((void**)&p_wrt, g_wrt);
    cudaGetSymbolAddress((void**)&p_wot, g_wot);
    cudaGetSymbolAddress((void**)&p_qwbf, g_qwbf);
    cudaGetSymbolAddress((void**)&p_qrbf, g_qrbf);
    cudaGetSymbolAddress((void**)&p_kbf, g_kbf);
    cudaGetSymbolAddress((void**)&p_rkbf, g_rkbf);
    cudaGetSymbolAddress((void**)&p_vtbf, g_vtbf);
    cudaGetSymbolAddress((void**)&p_vecbf, g_vecbf);

    cudaFuncSetAttribute(mma_gemm2<128, 128>, cudaFuncAttributeMaxDynamicSharedMemorySize, 131072);
    cudaFuncSetAttribute(flash_kernel, cudaFuncAttributeMaxDynamicSharedMemorySize, 198656);

    const int FULLMASK = 0x7FFFFFFF;
    constexpr int SM128 = 131072;

    split_kernel<<<4096 * 1024 / 256, 256>>>(w, p_wbf, 1024);                 // 0
    tsplit_kernel<<<dim3(16, 48), 256>>>(W_qkv, p_qkvt, 3072, 1024);          // 1

    mma_gemm2<128, 128><<<dim3(24, 32, 1), 256, SM128>>>(                     // 2: heads
        p_wbf, p_qkvt, p_heads, 1024, 2048, 2048, 3072, 0, 0, 0, 0, FULLMASK);

    split_kernel<<<1024 * 1024 / 256, 256>>>(r, p_rbf, 1024);                 // 3
    tsplit_kernel<<<dim3(16, 16), 256>>>(W_r, p_wrt, 1024, 1024);             // 4

    mma_gemm2<128, 128><<<dim3(8, 8, 1), 256, SM128>>>(                       // 5: r_k
        p_rbf, p_wrt, p_rk, 1024, 2048, 2048, 1024, 0, 0, 0, 0, FULLMASK);

    pack_qk_kernel<<<BN_TOT * QLEN * DH / 256, 256>>>(rwb, rrb);              // 6
    pack_rk_kernel<<<NH * QLEN * DH / 256, 256>>>();                          // 7
    pack_vt_kernel<<<dim3(16, 64), 256>>>();                                  // 8

    // BDrel = qr @ rk^T (anti-tri tiles, B batch = head), pre-scaled 0.125
    mma_gemm2<128, 128><<<dim3(36, 1, BN_TOT), 256, SM128>>>(                 // 9
        p_qrbf, p_rkbf, p_BD, 64, 128, 128, 1024,
        (long long)QLEN * 128, (long long)QLEN * 128, (long long)QLEN * QLEN,
        2, 15);

    // fused AC + BD + no-max softmax + PV
    flash_kernel<<<dim3(8, 1, BN_TOT), 256, 198656>>>();                      // 10

    tsplit_kernel<<<dim3(16, 16), 256>>>(W_o, p_wot, 1024, 1024);             // 11

    mma_gemm2<128, 128><<<dim3(8, 32, 1), 256, SM128>>>(                      // 12: attn
        p_vecbf, p_wot, p_attn, 1024, 2048, 2048, 1024, 0, 0, 0, 0, FULLMASK);

    ln_kernel<<<4096, 256>>>(w, gamma, beta, out);                            // 13
}

// round 12
// speedup vs baseline: 1.0928x; 1.0928x over previous
#include <cuda_runtime.h>
#include <cuda_bf16.h>
#include <cstdint>
#include <cstddef>

#define QLEN 1024
#define BSZ 4
#define DM 1024
#define NH 16
#define DH 64
#define BN_TOT 64
#define NEGINF -1e30f
#define KDIM 1024

__device__ __forceinline__ uint32_t smem_to_u32(const void* p) {
    uint32_t a;
    asm("{ .reg .u64 t; cvta.to.shared.u64 t, %1; cvt.u32.u64 %0, t; }" : "=r"(a) : "l"(p));
    return a;
}
#define SWZ128(b) ((b) ^ (((b) >> 3) & 0x70))

__device__ __forceinline__ void ldm_x4(uint32_t r[4], uint32_t addr) {
    asm volatile("ldmatrix.sync.aligned.m8n8.x4.shared.b16 {%0,%1,%2,%3}, [%4];"
                 : "=r"(r[0]), "=r"(r[1]), "=r"(r[2]), "=r"(r[3]) : "r"(addr));
}
__device__ __forceinline__ void mma16816(float c[4], const uint32_t a[4], const uint32_t b[2]) {
    asm volatile("mma.sync.aligned.m16n8k16.row.col.f32.bf16.bf16.f32 "
                 "{%0,%1,%2,%3}, {%4,%5,%6,%7}, {%8,%9}, {%0,%1,%2,%3};"
                 : "+f"(c[0]), "+f"(c[1]), "+f"(c[2]), "+f"(c[3])
                 : "r"(a[0]), "r"(a[1]), "r"(a[2]), "r"(a[3]), "r"(b[0]), "r"(b[1]));
}
__device__ __forceinline__ void cp_async16(uint32_t saddr, const void* gptr) {
    asm volatile("cp.async.cg.shared.global [%0], [%1], 16;" :: "r"(saddr), "l"(gptr));
}
__device__ __forceinline__ void cp_commit() { asm volatile("cp.async.commit_group;"); }
template <int N>
__device__ __forceinline__ void cp_wait() { asm volatile("cp.async.wait_group %0;" :: "n"(N)); }

// ---------------- scratch ----------------
__device__ float g_heads[(size_t)QLEN * BSZ * 3 * DM];
__device__ float g_rk[(size_t)QLEN * DM];
__device__ float g_BD[(size_t)BN_TOT * QLEN * QLEN];
__device__ float g_attn[(size_t)QLEN * BSZ * DM];
__device__ __nv_bfloat16 g_wbf[(size_t)QLEN * BSZ * 2 * KDIM];
__device__ __nv_bfloat16 g_rbf[(size_t)QLEN * 2 * KDIM];
__device__ __nv_bfloat16 g_qkvt[(size_t)3 * DM * 2 * KDIM];
__device__ __nv_bfloat16 g_wrt[(size_t)DM * 2 * KDIM];
__device__ __nv_bfloat16 g_wot[(size_t)DM * 2 * KDIM];
__device__ __nv_bfloat16 g_qwbf[(size_t)BN_TOT * QLEN * 2 * DH];   // pre-scaled by 0.125
__device__ __nv_bfloat16 g_qrbf[(size_t)BN_TOT * QLEN * 2 * DH];   // pre-scaled by 0.125
__device__ __nv_bfloat16 g_kbf[(size_t)BN_TOT * QLEN * 2 * DH];
__device__ __nv_bfloat16 g_rkbf[(size_t)NH * QLEN * 2 * DH];
__device__ __nv_bfloat16 g_vtbf[(size_t)BN_TOT * DH * 2 * QLEN];
__device__ __nv_bfloat16 g_vecbf[(size_t)QLEN * BSZ * 2 * KDIM];

__device__ __forceinline__ void split2(float x, __nv_bfloat16& h, __nv_bfloat16& l) {
    h = __float2bfloat16(x);
    l = __float2bfloat16(x - __bfloat162float(h));
}

// ---------------- HMMA GEMM: load-once 3-pass hi/lo ----------------
// mode 0: full grid; 2: anti-tri 8x8 (BD). zbase offsets blockIdx.z.
template <int BM, int BN>
__global__ __launch_bounds__(256) void mma_gemm2(
    const __nv_bfloat16* __restrict__ A, const __nv_bfloat16* __restrict__ Bt,
    float* __restrict__ C, int K, int lda, int ldb, int ldc,
    long long sA, long long sB, long long sC, int mode, int bmask, int zbase)
{
    extern __shared__ char smem[];
    const uint32_t smem_u32 = smem_to_u32(smem);
    constexpr int AHB = BM * 128;
    constexpr int BHB = BN * 128;
    constexpr int STG = 2 * AHB + 2 * BHB;
    constexpr int WN = BN / 2;
    constexpr int MT = 2;
    constexpr int NT = WN / 8;

    const int tid = threadIdx.x;
    const int lane = tid & 31, warp = tid >> 5;
    const int wm = warp & 3, wn = warp >> 2;
    const int bz = blockIdx.z + zbase;

    int m0, n0;
    if (mode == 0) {
        m0 = blockIdx.y * BM;
        n0 = blockIdx.x * BN;
    } else {
        int x = blockIdx.x;
        int it = (int)floorf((sqrtf(8.f * x + 1.f) - 1.f) * 0.5f);
        while ((it + 1) * (it + 2) / 2 <= x) ++it;
        while (it * (it + 1) / 2 > x) --it;
        int jt = x - it * (it + 1) / 2;
        m0 = it * BM;
        n0 = (7 - jt) * BN;
    }

    const __nv_bfloat16* Ab = A + (size_t)bz * sA;
    const __nv_bfloat16* Bb = Bt + (size_t)(bz & bmask) * sB;

    const int KT = K / 64;

    auto cp_stage = [&](int kt, int s) {
        const uint32_t base = smem_u32 + s * STG;
#pragma unroll
        for (int i = 0; i < BM / 32; i++) {
            int c = tid + i * 256, row = c >> 3, q = c & 7;
            uint32_t sw = SWZ128(row * 128 + q * 16);
            const __nv_bfloat16* gp = Ab + (size_t)(m0 + row) * lda + kt * 64 + q * 8;
            cp_async16(base + sw, gp);
            cp_async16(base + AHB + sw, gp + K);
        }
#pragma unroll
        for (int i = 0; i < BN / 32; i++) {
            int c = tid + i * 256, row = c >> 3, q = c & 7;
            uint32_t sw = SWZ128(row * 128 + q * 16);
            const __nv_bfloat16* gp = Bb + (size_t)(n0 + row) * ldb + kt * 64 + q * 8;
            cp_async16(base + 2 * AHB + sw, gp);
            cp_async16(base + 2 * AHB + BHB + sw, gp + K);
        }
        cp_commit();
    };

    float acc[MT][NT][4];
#pragma unroll
    for (int mt = 0; mt < MT; mt++)
#pragma unroll
        for (int nt = 0; nt < NT; nt++)
#pragma unroll
            for (int u = 0; u < 4; u++) acc[mt][nt][u] = 0.f;

    cp_stage(0, 0);
    if (KT > 1) cp_stage(1, 1);

    for (int t = 0; t < KT; t++) {
        const int s = t & 1;
        if (t < KT - 1) cp_wait<1>(); else cp_wait<0>();
        __syncthreads();

        const uint32_t ah = smem_u32 + s * STG;
        const uint32_t al = ah + AHB;
        const uint32_t bh = ah + 2 * AHB;
        const uint32_t bl = bh + BHB;
#pragma unroll
        for (int kk = 0; kk < 4; kk++) {
            const int seg = kk * 32 + (lane >> 4) * 16;
            uint32_t afh[MT][4], afl[MT][4], bfh[NT][2], bfl[NT][2];
#pragma unroll
            for (int mt = 0; mt < MT; mt++) {
                int sw = SWZ128((wm * 32 + mt * 16 + (lane & 15)) * 128 + seg);
                ldm_x4(afh[mt], ah + sw);
                ldm_x4(afl[mt], al + sw);
            }
#pragma unroll
            for (int p = 0; p < NT / 2; p++) {
                int sw = SWZ128((wn * WN + p * 16 + (lane & 15)) * 128 + seg);
                uint32_t r[4];
                ldm_x4(r, bh + sw);
                bfh[2 * p][0] = r[0]; bfh[2 * p][1] = r[2];
                bfh[2 * p + 1][0] = r[1]; bfh[2 * p + 1][1] = r[3];
                ldm_x4(r, bl + sw);
                bfl[2 * p][0] = r[0]; bfl[2 * p][1] = r[2];
                bfl[2 * p + 1][0] = r[1]; bfl[2 * p + 1][1] = r[3];
            }
#pragma unroll
            for (int mt = 0; mt < MT; mt++)
#pragma unroll
                for (int nt = 0; nt < NT; nt++)
                    mma16816(acc[mt][nt], afh[mt], bfh[nt]);
#pragma unroll
            for (int mt = 0; mt < MT; mt++)
#pragma unroll
                for (int nt = 0; nt < NT; nt++)
                    mma16816(acc[mt][nt], afl[mt], bfh[nt]);
#pragma unroll
            for (int mt = 0; mt < MT; mt++)
#pragma unroll
                for (int nt = 0; nt < NT; nt++)
                    mma16816(acc[mt][nt], afh[mt], bfl[nt]);
        }
        __syncthreads();
        if (t + 2 < KT) cp_stage(t + 2, s);
    }

    float* Cb = C + (size_t)bz * sC;
#pragma unroll
    for (int mt = 0; mt < MT; mt++)
#pragma unroll
        for (int nt = 0; nt < NT; nt++) {
            int mrow = m0 + wm * 32 + mt * 16 + (lane >> 2);
            int col = n0 + wn * WN + nt * 8 + (lane & 3) * 2;
            *(float2*)&Cb[(size_t)mrow * ldc + col] = make_float2(acc[mt][nt][0], acc[mt][nt][1]);
            *(float2*)&Cb[(size_t)(mrow + 8) * ldc + col] = make_float2(acc[mt][nt][2], acc[mt][nt][3]);
        }
}

// ---------------- flash kernel: AC(HMMA) + shifted BD + online softmax + PV (R9 structure) ----------------
__global__ __launch_bounds__(256) void flash_kernel(int zbase)
{
    extern __shared__ char smem[];
    const uint32_t su = smem_to_u32(smem);
    constexpr int OFF_QWH = 0, OFF_QWL = 16384;
    constexpr int OFF_K = 32768;
    constexpr int OFF_VH = 98304;
    constexpr int OFF_VL = 114688;
    constexpr int OFF_PH = 131072;
    constexpr int OFF_PL = 163840;
    constexpr int OFF_RA = 196608;
    constexpr int OFF_RB = 197632;

    const int tid = threadIdx.x;
    const int lane = tid & 31, warp = tid >> 5;
    const int wm = warp & 3, wn = warp >> 2;
    const int bn = blockIdx.z + zbase;
    const int it = 7 - blockIdx.x;
    const int i0 = it * 128;

    const __nv_bfloat16* qw = g_qwbf + (size_t)bn * QLEN * 128;
    const __nv_bfloat16* kb = g_kbf + (size_t)bn * QLEN * 128;
    const __nv_bfloat16* vt = g_vtbf + (size_t)bn * DH * 2048;
    const float* bdb = g_BD + (size_t)bn * QLEN * QLEN;
    float* redA = (float*)(smem + OFF_RA);
    float* redB = (float*)(smem + OFF_RB);

#pragma unroll
    for (int i = 0; i < 4; i++) {
        int c = tid + i * 256, row = c >> 3, q = c & 7;
        uint32_t sw = SWZ128(row * 128 + q * 16);
        const __nv_bfloat16* gp = qw + (size_t)(i0 + row) * 128 + q * 8;
        cp_async16(su + OFF_QWH + sw, gp);
        cp_async16(su + OFF_QWL + sw, gp + 64);
    }
#pragma unroll
    for (int i = 0; i < 4; i++) {
        int c = tid + i * 256, row = c >> 3, q = c & 7;
        uint32_t sw = SWZ128(row * 128 + q * 16);
        const __nv_bfloat16* gp = kb + (size_t)row * 128 + q * 8;
        cp_async16(su + OFF_K + sw, gp);
        cp_async16(su + OFF_K + 16384 + sw, gp + 64);
    }
    cp_commit();

    float acc_o[2][4][4];
#pragma unroll
    for (int mt = 0; mt < 2; mt++)
#pragma unroll
        for (int nt = 0; nt < 4; nt++)
#pragma unroll
            for (int u = 0; u < 4; u++) acc_o[mt][nt][u] = 0.f;
    float m_old[4], l_run[4];
#pragma unroll
    for (int i = 0; i < 4; i++) { m_old[i] = NEGINF; l_run[i] = 0.f; }

    for (int jt = 0; jt <= it; jt++) {
        const int s = jt & 1;
        const int j0 = jt * 128;
        const bool more = (jt < it);
        cp_wait<0>();
        __syncthreads();

#pragma unroll
        for (int i = 0; i < 8; i++) {
            int c = tid + i * 256;
            int q = c & 7, row = (c >> 3) & 63, ch = (c >> 9) & 1, hf = c >> 10;
            uint32_t sw = SWZ128(row * 128 + q * 16) + ch * 8192;
            const __nv_bfloat16* gp = vt + (size_t)row * 2048 + hf * 1024 + j0 + ch * 64 + q * 8;
            cp_async16(su + (hf ? OFF_VL : OFF_VH) + sw, gp);
        }
        cp_commit();
        if (more) {
            int j0n = j0 + 128;
#pragma unroll
            for (int i = 0; i < 4; i++) {
                int c = tid + i * 256, row = c >> 3, q = c & 7;
                uint32_t sw = SWZ128(row * 128 + q * 16);
                const __nv_bfloat16* gp = kb + (size_t)(j0n + row) * 128 + q * 8;
                cp_async16(su + OFF_K + (s ^ 1) * 32768 + sw, gp);
                cp_async16(su + OFF_K + (s ^ 1) * 32768 + 16384 + sw, gp + 64);
            }
            cp_commit();
        }

        float accS[2][8][4];
#pragma unroll
        for (int mt = 0; mt < 2; mt++)
#pragma unroll
            for (int nt = 0; nt < 8; nt++)
#pragma unroll
                for (int u = 0; u < 4; u++) accS[mt][nt][u] = 0.f;

        const uint32_t ah_ = su + OFF_QWH, al_ = su + OFF_QWL;
        const uint32_t bh_ = su + OFF_K + s * 32768, bl_ = bh_ + 16384;
#pragma unroll
        for (int kk = 0; kk < 4; kk++) {
            const int seg = kk * 32 + (lane >> 4) * 16;
            uint32_t afh[2][4], afl[2][4], bfh[8][2], bfl[8][2];
#pragma unroll
            for (int mt = 0; mt < 2; mt++) {
                int sw = SWZ128((wm * 32 + mt * 16 + (lane & 15)) * 128 + seg);
                ldm_x4(afh[mt], ah_ + sw);
                ldm_x4(afl[mt], al_ + sw);
            }
#pragma unroll
            for (int p = 0; p < 4; p++) {
                int sw = SWZ128((wn * 64 + p * 16 + (lane & 15)) * 128 + seg);
                uint32_t r[4];
                ldm_x4(r, bh_ + sw);
                bfh[2 * p][0] = r[0]; bfh[2 * p][1] = r[2];
                bfh[2 * p + 1][0] = r[1]; bfh[2 * p + 1][1] = r[3];
                ldm_x4(r, bl_ + sw);
                bfl[2 * p][0] = r[0]; bfl[2 * p][1] = r[2];
                bfl[2 * p + 1][0] = r[1]; bfl[2 * p + 1][1] = r[3];
            }
#pragma unroll
            for (int mt = 0; mt < 2; mt++)
#pragma unroll
                for (int nt = 0; nt < 8; nt++)
                    mma16816(accS[mt][nt], afh[mt], bfh[nt]);
#pragma unroll
            for (int mt = 0; mt < 2; mt++)
#pragma unroll
                for (int nt = 0; nt < 8; nt++)
                    mma16816(accS[mt][nt], afl[mt], bfh[nt]);
#pragma unroll
            for (int mt = 0; mt < 2; mt++)
#pragma unroll
                for (int nt = 0; nt < 8; nt++)
                    mma16816(accS[mt][nt], afh[mt], bfl[nt]);
        }

        // + shifted BD, causal mask (batched, registers)
#pragma unroll
        for (int mt = 0; mt < 2; mt++)
#pragma unroll
            for (int hf = 0; hf < 2; hf++) {
                int row_l = wm * 32 + mt * 16 + (lane >> 2) + hf * 8;
                int gi = i0 + row_l;
                const float* bdrow = bdb + (size_t)gi * 1024 + (1023 - gi) + j0;
#pragma unroll
                for (int nt = 0; nt < 8; nt++)
#pragma unroll
                    for (int e = 0; e < 2; e++) {
                        int col = wn * 64 + nt * 8 + (lane & 3) * 2 + e;
                        int gj = j0 + col;
                        float v = (gj <= gi) ? (accS[mt][nt][hf * 2 + e] + bdrow[col]) : NEGINF;
                        accS[mt][nt][hf * 2 + e] = v;
                    }
            }

        // online softmax: row max
        float m_new[4], alpha[4];
#pragma unroll
        for (int mt = 0; mt < 2; mt++)
#pragma unroll
            for (int hf = 0; hf < 2; hf++) {
                float mx = NEGINF;
#pragma unroll
                for (int nt = 0; nt < 8; nt++)
                    mx = fmaxf(mx, fmaxf(accS[mt][nt][hf * 2], accS[mt][nt][hf * 2 + 1]));
                mx = fmaxf(mx, __shfl_xor_sync(0xffffffffu, mx, 1));
                mx = fmaxf(mx, __shfl_xor_sync(0xffffffffu, mx, 2));
                if ((lane & 3) == 0) redA[wn * 128 + wm * 32 + mt * 16 + (lane >> 2) + hf * 8] = mx;
                m_new[mt * 2 + hf] = mx;
            }
        __syncthreads();
#pragma unroll
        for (int mt = 0; mt < 2; mt++)
#pragma unroll
            for (int hf = 0; hf < 2; hf++) {
                int row_l = wm * 32 + mt * 16 + (lane >> 2) + hf * 8;
                int idx = mt * 2 + hf;
                float comb = fmaxf(redA[row_l], redA[128 + row_l]);
                float mn = fmaxf(m_old[idx], comb);
                alpha[idx] = __expf(m_old[idx] - mn);
                m_new[idx] = mn;
                m_old[idx] = mn;
            }

        // p = exp(s - m), row sums
#pragma unroll
        for (int mt = 0; mt < 2; mt++)
#pragma unroll
            for (int hf = 0; hf < 2; hf++) {
                int idx = mt * 2 + hf;
                float ssum = 0.f;
#pragma unroll
                for (int nt = 0; nt < 8; nt++)
#pragma unroll
                    for (int e = 0; e < 2; e++) {
                        float p = __expf(accS[mt][nt][hf * 2 + e] - m_new[idx]);
                        accS[mt][nt][hf * 2 + e] = p;
                        ssum += p;
                    }
                ssum += __shfl_xor_sync(0xffffffffu, ssum, 1);
                ssum += __shfl_xor_sync(0xffffffffu, ssum, 2);
                if ((lane & 3) == 0) redB[wn * 128 + wm * 32 + mt * 16 + (lane >> 2) + hf * 8] = ssum;
            }
        __syncthreads();
#pragma unroll
        for (int mt = 0; mt < 2; mt++)
#pragma unroll
            for (int hf = 0; hf < 2; hf++) {
                int row_l = wm * 32 + mt * 16 + (lane >> 2) + hf * 8;
                int idx = mt * 2 + hf;
                l_run[idx] = l_run[idx] * alpha[idx] + redB[row_l] + redB[128 + row_l];
            }

        // rescale acc_o
#pragma unroll
        for (int mt = 0; mt < 2; mt++)
#pragma unroll
            for (int nt = 0; nt < 4; nt++)
#pragma unroll
                for (int u = 0; u < 4; u++) acc_o[mt][nt][u] *= alpha[mt * 2 + (u >> 1)];

        // store P (split bf16)
#pragma unroll
        for (int mt = 0; mt < 2; mt++)
#pragma unroll
            for (int hf = 0; hf < 2; hf++) {
                int row_l = wm * 32 + mt * 16 + (lane >> 2) + hf * 8;
#pragma unroll
                for (int nt = 0; nt < 8; nt++) {
                    float v0 = accS[mt][nt][hf * 2], v1 = accS[mt][nt][hf * 2 + 1];
                    __nv_bfloat16 h0, l0, h1, l1;
                    split2(v0, h0, l0);
                    split2(v1, h1, l1);
                    uint32_t off = SWZ128(row_l * 128 + (nt * 8 + (lane & 3) * 2) * 2);
                    *(__nv_bfloat162*)(smem + OFF_PH + wn * 16384 + off) = __nv_bfloat162(h0, h1);
                    *(__nv_bfloat162*)(smem + OFF_PL + wn * 16384 + off) = __nv_bfloat162(l0, l1);
                }
            }
        if (more) cp_wait<1>(); else cp_wait<0>();
        __syncthreads();

        // PV: acc_o += P @ V
#pragma unroll
        for (int kk = 0; kk < 8; kk++) {
            const int ch = kk >> 2;
            const int seg = (kk & 3) * 32 + (lane >> 4) * 16;
            uint32_t pah[2][4], pal[2][4], vbh[4][2], vbl[4][2];
#pragma unroll
            for (int mt = 0; mt < 2; mt++) {
                int sw = SWZ128((wm * 32 + mt * 16 + (lane & 15)) * 128 + seg);
                ldm_x4(pah[mt], su + OFF_PH + ch * 16384 + sw);
                ldm_x4(pal[mt], su + OFF_PL + ch * 16384 + sw);
            }
#pragma unroll
            for (int p = 0; p < 2; p++) {
                int sw = SWZ128((wn * 32 + p * 16 + (lane & 15)) * 128 + seg);
                uint32_t r[4];
                ldm_x4(r, su + OFF_VH + ch * 8192 + sw);
                vbh[2 * p][0] = r[0]; vbh[2 * p][1] = r[2];
                vbh[2 * p + 1][0] = r[1]; vbh[2 * p + 1][1] = r[3];
                ldm_x4(r, su + OFF_VL + ch * 8192 + sw);
                vbl[2 * p][0] = r[0]; vbl[2 * p][1] = r[2];
                vbl[2 * p + 1][0] = r[1]; vbl[2 * p + 1][1] = r[3];
            }
#pragma unroll
            for (int mt = 0; mt < 2; mt++)
#pragma unroll
                for (int nt = 0; nt < 4; nt++)
                    mma16816(acc_o[mt][nt], pah[mt], vbh[nt]);
#pragma unroll
            for (int mt = 0; mt < 2; mt++)
#pragma unroll
                for (int nt = 0; nt < 4; nt++)
                    mma16816(acc_o[mt][nt], pal[mt], vbh[nt]);
#pragma unroll
            for (int mt = 0; mt < 2; mt++)
#pragma unroll
                for (int nt = 0; nt < 4; nt++)
                    mma16816(acc_o[mt][nt], pah[mt], vbl[nt]);
        }
        __syncthreads();
    }

    // epilogue
    const int b = bn >> 4, n = bn & 15;
    float inv[4];
#pragma unroll
    for (int i = 0; i < 4; i++) inv[i] = 1.f / l_run[i];
#pragma unroll
    for (int mt = 0; mt < 2; mt++)
#pragma unroll
        for (int nt = 0; nt < 4; nt++)
#pragma unroll
            for (int hf = 0; hf < 2; hf++) {
                int row_l = wm * 32 + mt * 16 + (lane >> 2) + hf * 8;
                int gi = i0 + row_l;
                int d0 = wn * 32 + nt * 8 + (lane & 3) * 2;
                float v0 = acc_o[mt][nt][hf * 2] * inv[mt * 2 + hf];
                float v1 = acc_o[mt][nt][hf * 2 + 1] * inv[mt * 2 + hf];
                __nv_bfloat16 h0, l0, h1, l1;
                split2(v0, h0, l0);
                split2(v1, h1, l1);
                size_t orow = (size_t)(gi * 4 + b) * 2048 + n * 64 + d0;
                *(__nv_bfloat162*)&g_vecbf[orow] = __nv_bfloat162(h0, h1);
                *(__nv_bfloat162*)&g_vecbf[orow + 1024] = __nv_bfloat162(l0, l1);
            }
}

// ---------------- split / transpose / pack kernels ----------------
__global__ void split_kernel(const float* __restrict__ X, __nv_bfloat16* __restrict__ Y, int cols)
{
    int idx = blockIdx.x * 256 + threadIdx.x;
    int row = idx / cols, col = idx - row * cols;
    __nv_bfloat16 h, l;
    split2(X[idx], h, l);
    Y[(size_t)row * 2 * cols + col] = h;
    Y[(size_t)row * 2 * cols + cols + col] = l;
}

__global__ __launch_bounds__(256) void tsplit_kernel(const float* __restrict__ X,
                                                     __nv_bfloat16* __restrict__ Y, int N, int K)
{
    __shared__ float sm[64][65];
    int k0 = blockIdx.x * 64, n0 = blockIdx.y * 64;
    int tid = threadIdx.x;
    for (int e = tid; e < 4096; e += 256) {
        int r = e >> 6, c = e & 63;
        sm[c][r] = X[(size_t)(k0 + r) * N + n0 + c];
    }
    __syncthreads();
    for (int e = tid; e < 4096; e += 256) {
        int r = e >> 6, c = e & 63;
        __nv_bfloat16 h, l;
        split2(sm[r][c], h, l);
        Y[(size_t)(n0 + r) * 2 * K + k0 + c] = h;
        Y[(size_t)(n0 + r) * 2 * K + K + k0 + c] = l;
    }
}

__global__ void pack_qk_kernel(const float* __restrict__ rwb, const float* __restrict__ rrb)
{
    int idx = blockIdx.x * 256 + threadIdx.x;
    int d = idx & 63, i = (idx >> 6) & 1023, bn = idx >> 16;
    int b = bn >> 4, n = bn & 15;
    size_t hbase = (size_t)(i * 4 + b) * 3072 + n * 64 + d;
    float q = g_heads[hbase];
    float k = g_heads[hbase + 1024];
    size_t o = ((size_t)bn * QLEN + i) * 128 + d;
    __nv_bfloat16 h, l;
    split2((q + rwb[n * 64 + d]) * 0.125f, h, l);
    g_qwbf[o] = h; g_qwbf[o + 64] = l;
    split2((q + rrb[n * 64 + d]) * 0.125f, h, l);
    g_qrbf[o] = h; g_qrbf[o + 64] = l;
    split2(k, h, l);
    g_kbf[o] = h; g_kbf[o + 64] = l;
}

__global__ void pack_rk_kernel()
{
    int idx = blockIdx.x * 256 + threadIdx.x;
    int d = idx & 63, m = (idx >> 6) & 1023, n = idx >> 16;
    __nv_bfloat16 h, l;
    split2(g_rk[(size_t)m * 1024 + n * 64 + d], h, l);
    size_t o = ((size_t)n * QLEN + m) * 128 + d;
    g_rkbf[o] = h; g_rkbf[o + 64] = l;
}

__global__ __launch_bounds__(256) void pack_vt_kernel()
{
    __shared__ float sm[64][65];
    int bn = blockIdx.y, b = bn >> 4, n = bn & 15;
    int j0 = blockIdx.x * 64;
    int tid = threadIdx.x;
    for (int e = tid; e < 4096; e += 256) {
        int jj = e >> 6, d = e & 63;
        sm[d][jj] = g_heads[(size_t)((j0 + jj) * 4 + b) * 3072 + 2048 + n * 64 + d];
    }
    __syncthreads();
    for (int e = tid; e < 4096; e += 256) {
        int d = e >> 6, jj = e & 63;
        __nv_bfloat16 h, l;
        split2(sm[d][jj], h, l);
        g_vtbf[((size_t)bn * 64 + d) * 2048 + j0 + jj] = h;
        g_vtbf[((size_t)bn * 64 + d) * 2048 + 1024 + j0 + jj] = l;
    }
}

// ---------------- residual + layernorm ----------------
__global__ __launch_bounds__(256) void ln_kernel(
    const float* __restrict__ w, const float* __restrict__ gamma,
    const float* __restrict__ beta, float* __restrict__ out)
{
    int row = blockIdx.x;
    const float* wr = w + (size_t)row * DM;
    const float* ar = g_attn + (size_t)row * DM;
    int tid = threadIdx.x;

    float x[4];
    float s = 0.f, s2 = 0.f;
#pragma unroll
    for (int u = 0; u < 4; u++) {
        int c = tid + u * 256;
        x[u] = wr[c] + ar[c];
        s += x[u];
        s2 += x[u] * x[u];
    }
    __shared__ float rs[256], rs2[256];
    rs[tid] = s; rs2[tid] = s2;
    __syncthreads();
    for (int t = 128; t > 0; t >>= 1) {
        if (tid < t) { rs[tid] += rs[tid + t]; rs2[tid] += rs2[tid + t]; }
        __syncthreads();
    }
    float mu = rs[0] * (1.f / DM);
    float var = rs2[0] * (1.f / DM) - mu * mu;
    float rstd = rsqrtf(var + 1e-5f);
#pragma unroll
    for (int u = 0; u < 4; u++) {
        int c = tid + u * 256;
        out[(size_t)row * DM + c] = (x[u] - mu) * rstd * gamma[c] + beta[c];
    }
}

// ---------------- launch ----------------
extern "C" void kernel_launch(void* const* d_in, const int* in_sizes, int n_in,
                              void* d_out, int out_size)
{
    const float* w     = (const float*)d_in[0];
    const float* r     = (const float*)d_in[1];
    const float* rwb   = (const float*)d_in[2];
    const float* rrb   = (const float*)d_in[3];
    const float* W_qkv = (const float*)d_in[5];
    const float* W_r   = (const float*)d_in[6];
    const float* W_o   = (const float*)d_in[7];
    const float* gamma = (const float*)d_in[8];
    const float* beta  = (const float*)d_in[9];
    float* out = (float*)d_out;

    float *p_heads, *p_rk, *p_BD, *p_attn;
    __nv_bfloat16 *p_wbf, *p_rbf, *p_qkvt, *p_wrt, *p_wot;
    __nv_bfloat16 *p_qwbf, *p_qrbf, *p_kbf, *p_rkbf, *p_vtbf, *p_vecbf;
    cudaGetSymbolAddress((void**)&p_heads, g_heads);
    cudaGetSymbolAddress((void**)&p_rk, g_rk);
    cudaGetSymbolAddress((void**)&p_BD, g_BD);
    cudaGetSymbolAddress((void**)&p_attn, g_attn);
    cudaGetSymbolAddress((void**)&p_wbf, g_wbf);
    cudaGetSymbolAddress((void**)&p_rbf, g_rbf);
    cudaGetSymbolAddress((void**)&p_qkvt, g_qkvt);
    cudaGetSymbolAddress((void**)&p_wrt, g_wrt);
    cudaGetSymbolAddress((void**)&p_wot, g_wot);
    cudaGetSymbolAddress((void**)&p_qwbf, g_qwbf);
    cudaGetSymbolAddress((void**)&p_qrbf, g_qrbf);
    cudaGetSymbolAddress((void**)&p_kbf, g_kbf);
    cudaGetSymbolAddress((void**)&p_rkbf, g_rkbf);
    cudaGetSymbolAddress((void**)&p_vtbf, g_vtbf);
    cudaGetSymbolAddress((void**)&p_vecbf, g_vecbf);

    cudaFuncSetAttribute(mma_gemm2<128, 128>, cudaFuncAttributeMaxDynamicSharedMemorySize, 131072);
    cudaFuncSetAttribute(flash_kernel, cudaFuncAttributeMaxDynamicSharedMemorySize, 198656);

    const int FULLMASK = 0x7FFFFFFF;
    constexpr int SM128 = 131072;

    // second stream + events; every fork is joined back into stream 0
    cudaStream_t s2;
    cudaStreamCreateWithFlags(&s2, cudaStreamNonBlocking);
    cudaEvent_t e_start, e_r, e_wo, e_pack, e_bd1;
    cudaEventCreateWithFlags(&e_start, cudaEventDisableTiming);
    cudaEventCreateWithFlags(&e_r, cudaEventDisableTiming);
    cudaEventCreateWithFlags(&e_wo, cudaEventDisableTiming);
    cudaEventCreateWithFlags(&e_pack, cudaEventDisableTiming);
    cudaEventCreateWithFlags(&e_bd1, cudaEventDisableTiming);

    cudaEventRecord(e_start, 0);
    cudaStreamWaitEvent(s2, e_start, 0);

    // ---- stream 2: independent r-chain + W_o split ----
    split_kernel<<<1024 * 1024 / 256, 256, 0, s2>>>(r, p_rbf, 1024);
    tsplit_kernel<<<dim3(16, 16), 256, 0, s2>>>(W_r, p_wrt, 1024, 1024);
    mma_gemm2<128, 128><<<dim3(8, 8, 1), 256, SM128, s2>>>(
        p_rbf, p_wrt, p_rk, 1024, 2048, 2048, 1024, 0, 0, 0, 0, FULLMASK, 0);
    pack_rk_kernel<<<NH * QLEN * DH / 256, 256, 0, s2>>>();
    cudaEventRecord(e_r, s2);
    tsplit_kernel<<<dim3(16, 16), 256, 0, s2>>>(W_o, p_wot, 1024, 1024);
    cudaEventRecord(e_wo, s2);

    // ---- stream 0: QKV chain ----
    split_kernel<<<4096 * 1024 / 256, 256>>>(w, p_wbf, 1024);
    tsplit_kernel<<<dim3(16, 48), 256>>>(W_qkv, p_qkvt, 3072, 1024);
    mma_gemm2<128, 128><<<dim3(24, 32, 1), 256, SM128>>>(
        p_wbf, p_qkvt, p_heads, 1024, 2048, 2048, 3072, 0, 0, 0, 0, FULLMASK, 0);
    pack_qk_kernel<<<BN_TOT * QLEN * DH / 256, 256>>>(rwb, rrb);
    pack_vt_kernel<<<dim3(16, 64), 256>>>();
    cudaEventRecord(e_pack, 0);

    // ---- stream 2: BD group 1 (bn 32..63) overlaps flash group 0 ----
    cudaStreamWaitEvent(s2, e_pack, 0);
    mma_gemm2<128, 128><<<dim3(36, 1, 32), 256, SM128, s2>>>(
        p_qrbf, p_rkbf, p_BD, 64, 128, 128, 1024,
        (long long)QLEN * 128, (long long)QLEN * 128, (long long)QLEN * QLEN,
        2, 15, 32);
    cudaEventRecord(e_bd1, s2);

    // ---- stream 0: BD group 0, flash group 0 ----
    cudaStreamWaitEvent(0, e_r, 0);
    mma_gemm2<128, 128><<<dim3(36, 1, 32), 256, SM128>>>(
        p_qrbf, p_rkbf, p_BD, 64, 128, 128, 1024,
        (long long)QLEN * 128, (long long)QLEN * 128, (long long)QLEN * QLEN,
        2, 15, 0);
    flash_kernel<<<dim3(8, 1, 32), 256, 198656>>>(0);

    // ---- stream 0: flash group 1 after BD(g1) join ----
    cudaStreamWaitEvent(0, e_bd1, 0);
    flash_kernel<<<dim3(8, 1, 32), 256, 198656>>>(32);

    // ---- join W_o split, then attn out + layernorm ----
    cudaStreamWaitEvent(0, e_wo, 0);
    mma_gemm2<128, 128><<<dim3(8, 32, 1), 256, SM128>>>(
        p_vecbf, p_wot, p_attn, 1024, 2048, 2048, 1024, 0, 0, 0, 0, FULLMASK, 0);
    ln_kernel<<<4096, 256>>>(w, gamma, beta, out);
}

// round 15
// speedup vs baseline: 1.1206x; 1.0254x over previous
#include <cuda_runtime.h>
#include <cuda_bf16.h>
#include <cstdint>
#include <cstddef>

#define QLEN 1024
#define BSZ 4
#define DM 1024
#define NH 16
#define DH 64
#define BN_TOT 64
#define NEGINF -1e30f
#define KDIM 1024

__device__ __forceinline__ uint32_t smem_to_u32(const void* p) {
    uint32_t a;
    asm("{ .reg .u64 t; cvta.to.shared.u64 t, %1; cvt.u32.u64 %0, t; }" : "=r"(a) : "l"(p));
    return a;
}
#define SWZ128(b) ((b) ^ (((b) >> 3) & 0x70))

__device__ __forceinline__ void ldm_x4(uint32_t r[4], uint32_t addr) {
    asm volatile("ldmatrix.sync.aligned.m8n8.x4.shared.b16 {%0,%1,%2,%3}, [%4];"
                 : "=r"(r[0]), "=r"(r[1]), "=r"(r[2]), "=r"(r[3]) : "r"(addr));
}
__device__ __forceinline__ void mma16816(float c[4], const uint32_t a[4], const uint32_t b[2]) {
    asm volatile("mma.sync.aligned.m16n8k16.row.col.f32.bf16.bf16.f32 "
                 "{%0,%1,%2,%3}, {%4,%5,%6,%7}, {%8,%9}, {%0,%1,%2,%3};"
                 : "+f"(c[0]), "+f"(c[1]), "+f"(c[2]), "+f"(c[3])
                 : "r"(a[0]), "r"(a[1]), "r"(a[2]), "r"(a[3]), "r"(b[0]), "r"(b[1]));
}
__device__ __forceinline__ void cp_async16(uint32_t saddr, const void* gptr) {
    asm volatile("cp.async.cg.shared.global [%0], [%1], 16;" :: "r"(saddr), "l"(gptr));
}
__device__ __forceinline__ void cp_commit() { asm volatile("cp.async.commit_group;"); }
template <int N>
__device__ __forceinline__ void cp_wait() { asm volatile("cp.async.wait_group %0;" :: "n"(N)); }

// ---------------- scratch ----------------
__device__ float g_heads[(size_t)QLEN * BSZ * 3 * DM];     // only V third is written/read
__device__ float g_BD[(size_t)BN_TOT * QLEN * QLEN];
__device__ float g_attn[(size_t)QLEN * BSZ * DM];
__device__ __nv_bfloat16 g_wbf[(size_t)QLEN * BSZ * 2 * KDIM];
__device__ __nv_bfloat16 g_rbf[(size_t)QLEN * 2 * KDIM];
__device__ __nv_bfloat16 g_qkvt[(size_t)3 * DM * 2 * KDIM];
__device__ __nv_bfloat16 g_wrt[(size_t)DM * 2 * KDIM];
__device__ __nv_bfloat16 g_wot[(size_t)DM * 2 * KDIM];
__device__ __nv_bfloat16 g_qwbf[(size_t)BN_TOT * QLEN * 2 * DH];   // pre-scaled by 0.125
__device__ __nv_bfloat16 g_qrbf[(size_t)BN_TOT * QLEN * 2 * DH];   // pre-scaled by 0.125
__device__ __nv_bfloat16 g_kbf[(size_t)BN_TOT * QLEN * 2 * DH];
__device__ __nv_bfloat16 g_rkbf[(size_t)NH * QLEN * 2 * DH];
__device__ __nv_bfloat16 g_vtbf[(size_t)BN_TOT * DH * 2 * QLEN];
__device__ __nv_bfloat16 g_vecbf[(size_t)QLEN * BSZ * 2 * KDIM];

__device__ __forceinline__ void split2(float x, __nv_bfloat16& h, __nv_bfloat16& l) {
    h = __float2bfloat16(x);
    l = __float2bfloat16(x - __bfloat162float(h));
}
__device__ __forceinline__ void split_store(__nv_bfloat16* base, float v0, float v1) {
    __nv_bfloat16 h0, l0, h1, l1;
    split2(v0, h0, l0);
    split2(v1, h1, l1);
    *(__nv_bfloat162*)base = __nv_bfloat162(h0, h1);
    *(__nv_bfloat162*)(base + 64) = __nv_bfloat162(l0, l1);
}

// ---------------- HMMA GEMM: load-once 3-pass hi/lo, ONE instantiation ----------------
// mode 0: full grid; 2: anti-tri 8x8 (BD)
// epi (runtime): 0 fp32 C; 2 QKV fused pack; 3 rk split pack.
__global__ __launch_bounds__(256) void mma_gemm2(
    const __nv_bfloat16* __restrict__ A, const __nv_bfloat16* __restrict__ Bt,
    float* __restrict__ C, int K, int lda, int ldb, int ldc,
    long long sA, long long sB, long long sC, int mode, int bmask, int epi,
    const float* __restrict__ bias1, const float* __restrict__ bias2)
{
    extern __shared__ char smem[];
    const uint32_t smem_u32 = smem_to_u32(smem);
    constexpr int BM = 128, BN = 128;
    constexpr int AHB = BM * 128;
    constexpr int BHB = BN * 128;
    constexpr int STG = 2 * AHB + 2 * BHB;
    constexpr int WN = BN / 2;
    constexpr int MT = 2;
    constexpr int NT = WN / 8;

    const int tid = threadIdx.x;
    const int lane = tid & 31, warp = tid >> 5;
    const int wm = warp & 3, wn = warp >> 2;
    const int bz = blockIdx.z;

    int m0, n0;
    if (mode == 0) {
        m0 = blockIdx.y * BM;
        n0 = blockIdx.x * BN;
    } else {
        int x = blockIdx.x;
        int it = (int)floorf((sqrtf(8.f * x + 1.f) - 1.f) * 0.5f);
        while ((it + 1) * (it + 2) / 2 <= x) ++it;
        while (it * (it + 1) / 2 > x) --it;
        int jt = x - it * (it + 1) / 2;
        m0 = it * BM;
        n0 = (7 - jt) * BN;
    }

    const __nv_bfloat16* Ab = A + (size_t)bz * sA;
    const __nv_bfloat16* Bb = Bt + (size_t)(bz & bmask) * sB;

    const int KT = K / 64;

    auto cp_stage = [&](int kt, int s) {
        const uint32_t base = smem_u32 + s * STG;
#pragma unroll
        for (int i = 0; i < BM / 32; i++) {
            int c = tid + i * 256, row = c >> 3, q = c & 7;
            uint32_t sw = SWZ128(row * 128 + q * 16);
            const __nv_bfloat16* gp = Ab + (size_t)(m0 + row) * lda + kt * 64 + q * 8;
            cp_async16(base + sw, gp);
            cp_async16(base + AHB + sw, gp + K);
        }
#pragma unroll
        for (int i = 0; i < BN / 32; i++) {
            int c = tid + i * 256, row = c >> 3, q = c & 7;
            uint32_t sw = SWZ128(row * 128 + q * 16);
            const __nv_bfloat16* gp = Bb + (size_t)(n0 + row) * ldb + kt * 64 + q * 8;
            cp_async16(base + 2 * AHB + sw, gp);
            cp_async16(base + 2 * AHB + BHB + sw, gp + K);
        }
        cp_commit();
    };

    float acc[MT][NT][4];
#pragma unroll
    for (int mt = 0; mt < MT; mt++)
#pragma unroll
        for (int nt = 0; nt < NT; nt++)
#pragma unroll
            for (int u = 0; u < 4; u++) acc[mt][nt][u] = 0.f;

    cp_stage(0, 0);
    if (KT > 1) cp_stage(1, 1);

    for (int t = 0; t < KT; t++) {
        const int s = t & 1;
        if (t < KT - 1) cp_wait<1>(); else cp_wait<0>();
        __syncthreads();

        const uint32_t ah = smem_u32 + s * STG;
        const uint32_t al = ah + AHB;
        const uint32_t bh = ah + 2 * AHB;
        const uint32_t bl = bh + BHB;
#pragma unroll
        for (int kk = 0; kk < 4; kk++) {
            const int seg = kk * 32 + (lane >> 4) * 16;
            uint32_t afh[MT][4], afl[MT][4], bfh[NT][2], bfl[NT][2];
#pragma unroll
            for (int mt = 0; mt < MT; mt++) {
                int sw = SWZ128((wm * 32 + mt * 16 + (lane & 15)) * 128 + seg);
                ldm_x4(afh[mt], ah + sw);
                ldm_x4(afl[mt], al + sw);
            }
#pragma unroll
            for (int p = 0; p < NT / 2; p++) {
                int sw = SWZ128((wn * WN + p * 16 + (lane & 15)) * 128 + seg);
                uint32_t r[4];
                ldm_x4(r, bh + sw);
                bfh[2 * p][0] = r[0]; bfh[2 * p][1] = r[2];
                bfh[2 * p + 1][0] = r[1]; bfh[2 * p + 1][1] = r[3];
                ldm_x4(r, bl + sw);
                bfl[2 * p][0] = r[0]; bfl[2 * p][1] = r[2];
                bfl[2 * p + 1][0] = r[1]; bfl[2 * p + 1][1] = r[3];
            }
#pragma unroll
            for (int mt = 0; mt < MT; mt++)
#pragma unroll
                for (int nt = 0; nt < NT; nt++)
                    mma16816(acc[mt][nt], afh[mt], bfh[nt]);
#pragma unroll
            for (int mt = 0; mt < MT; mt++)
#pragma unroll
                for (int nt = 0; nt < NT; nt++)
                    mma16816(acc[mt][nt], afl[mt], bfh[nt]);
#pragma unroll
            for (int mt = 0; mt < MT; mt++)
#pragma unroll
                for (int nt = 0; nt < NT; nt++)
                    mma16816(acc[mt][nt], afh[mt], bfl[nt]);
        }
        __syncthreads();
        if (t + 2 < KT) cp_stage(t + 2, s);
    }

    if (epi == 0) {
        float* Cb = C + (size_t)bz * sC;
#pragma unroll
        for (int mt = 0; mt < MT; mt++)
#pragma unroll
            for (int nt = 0; nt < NT; nt++) {
                int mrow = m0 + wm * 32 + mt * 16 + (lane >> 2);
                int col = n0 + wn * WN + nt * 8 + (lane & 3) * 2;
                *(float2*)&Cb[(size_t)mrow * ldc + col] = make_float2(acc[mt][nt][0], acc[mt][nt][1]);
                *(float2*)&Cb[(size_t)(mrow + 8) * ldc + col] = make_float2(acc[mt][nt][2], acc[mt][nt][3]);
            }
    } else if (epi == 2) {
        // QKV fused pack: q -> qw/qr (bias+scale), k -> kbf, v -> g_heads
#pragma unroll
        for (int mt = 0; mt < MT; mt++)
#pragma unroll
            for (int nt = 0; nt < NT; nt++)
#pragma unroll
                for (int half = 0; half < 2; half++) {
                    int row = m0 + wm * 32 + mt * 16 + (lane >> 2) + half * 8;  // i*4+b
                    int col = n0 + wn * WN + nt * 8 + (lane & 3) * 2;
                    float v0 = acc[mt][nt][half * 2], v1 = acc[mt][nt][half * 2 + 1];
                    int region = col >> 10;
                    int cm = col & 1023;
                    int nh = cm >> 6, d0 = cm & 63;
                    int i = row >> 2, b = row & 3;
                    int bn = b * 16 + nh;
                    if (region == 0) {
                        size_t o = ((size_t)bn * QLEN + i) * 128 + d0;
                        float b1a = __ldg(&bias1[cm]), b1b = __ldg(&bias1[cm + 1]);
                        float b2a = __ldg(&bias2[cm]), b2b = __ldg(&bias2[cm + 1]);
                        split_store(&g_qwbf[o], (v0 + b1a) * 0.125f, (v1 + b1b) * 0.125f);
                        split_store(&g_qrbf[o], (v0 + b2a) * 0.125f, (v1 + b2b) * 0.125f);
                    } else if (region == 1) {
                        size_t o = ((size_t)bn * QLEN + i) * 128 + d0;
                        split_store(&g_kbf[o], v0, v1);
                    } else {
                        *(float2*)&g_heads[(size_t)row * 3072 + col] = make_float2(v0, v1);
                    }
                }
    } else {
        // epi == 3: rk split pack. row = m, col = nh*64+d0.
#pragma unroll
        for (int mt = 0; mt < MT; mt++)
#pragma unroll
            for (int nt = 0; nt < NT; nt++)
#pragma unroll
                for (int half = 0; half < 2; half++) {
                    int row = m0 + wm * 32 + mt * 16 + (lane >> 2) + half * 8;
                    int col = n0 + wn * WN + nt * 8 + (lane & 3) * 2;
                    int nh = col >> 6, d0 = col & 63;
                    size_t o = ((size_t)nh * QLEN + row) * 128 + d0;
                    split_store(&g_rkbf[o], acc[mt][nt][half * 2], acc[mt][nt][half * 2 + 1]);
                }
    }
}

// ---------------- flash kernel: AC(HMMA) + shifted BD + online softmax + PV (R9) ----------------
__global__ __launch_bounds__(256) void flash_kernel()
{
    extern __shared__ char smem[];
    const uint32_t su = smem_to_u32(smem);
    constexpr int OFF_QWH = 0, OFF_QWL = 16384;
    constexpr int OFF_K = 32768;
    constexpr int OFF_VH = 98304;
    constexpr int OFF_VL = 114688;
    constexpr int OFF_PH = 131072;
    constexpr int OFF_PL = 163840;
    constexpr int OFF_RA = 196608;
    constexpr int OFF_RB = 197632;

    const int tid = threadIdx.x;
    const int lane = tid & 31, warp = tid >> 5;
    const int wm = warp & 3, wn = warp >> 2;
    const int bn = blockIdx.z;
    const int it = 7 - blockIdx.x;
    const int i0 = it * 128;

    const __nv_bfloat16* qw = g_qwbf + (size_t)bn * QLEN * 128;
    const __nv_bfloat16* kb = g_kbf + (size_t)bn * QLEN * 128;
    const __nv_bfloat16* vt = g_vtbf + (size_t)bn * DH * 2048;
    const float* bdb = g_BD + (size_t)bn * QLEN * QLEN;
    float* redA = (float*)(smem + OFF_RA);
    float* redB = (float*)(smem + OFF_RB);

#pragma unroll
    for (int i = 0; i < 4; i++) {
        int c = tid + i * 256, row = c >> 3, q = c & 7;
        uint32_t sw = SWZ128(row * 128 + q * 16);
        const __nv_bfloat16* gp = qw + (size_t)(i0 + row) * 128 + q * 8;
        cp_async16(su + OFF_QWH + sw, gp);
        cp_async16(su + OFF_QWL + sw, gp + 64);
    }
#pragma unroll
    for (int i = 0; i < 4; i++) {
        int c = tid + i * 256, row = c >> 3, q = c & 7;
        uint32_t sw = SWZ128(row * 128 + q * 16);
        const __nv_bfloat16* gp = kb + (size_t)row * 128 + q * 8;
        cp_async16(su + OFF_K + sw, gp);
        cp_async16(su + OFF_K + 16384 + sw, gp + 64);
    }
    cp_commit();

    float acc_o[2][4][4];
#pragma unroll
    for (int mt = 0; mt < 2; mt++)
#pragma unroll
        for (int nt = 0; nt < 4; nt++)
#pragma unroll
            for (int u = 0; u < 4; u++) acc_o[mt][nt][u] = 0.f;
    float m_old[4], l_run[4];
#pragma unroll
    for (int i = 0; i < 4; i++) { m_old[i] = NEGINF; l_run[i] = 0.f; }

    for (int jt = 0; jt <= it; jt++) {
        const int s = jt & 1;
        const int j0 = jt * 128;
        const bool more = (jt < it);
        cp_wait<0>();
        __syncthreads();

#pragma unroll
        for (int i = 0; i < 8; i++) {
            int c = tid + i * 256;
            int q = c & 7, row = (c >> 3) & 63, ch = (c >> 9) & 1, hf = c >> 10;
            uint32_t sw = SWZ128(row * 128 + q * 16) + ch * 8192;
            const __nv_bfloat16* gp = vt + (size_t)row * 2048 + hf * 1024 + j0 + ch * 64 + q * 8;
            cp_async16(su + (hf ? OFF_VL : OFF_VH) + sw, gp);
        }
        cp_commit();
        if (more) {
            int j0n = j0 + 128;
#pragma unroll
            for (int i = 0; i < 4; i++) {
                int c = tid + i * 256, row = c >> 3, q = c & 7;
                uint32_t sw = SWZ128(row * 128 + q * 16);
                const __nv_bfloat16* gp = kb + (size_t)(j0n + row) * 128 + q * 8;
                cp_async16(su + OFF_K + (s ^ 1) * 32768 + sw, gp);
                cp_async16(su + OFF_K + (s ^ 1) * 32768 + 16384 + sw, gp + 64);
            }
            cp_commit();
        }

        float accS[2][8][4];
#pragma unroll
        for (int mt = 0; mt < 2; mt++)
#pragma unroll
            for (int nt = 0; nt < 8; nt++)
#pragma unroll
                for (int u = 0; u < 4; u++) accS[mt][nt][u] = 0.f;

        const uint32_t ah_ = su + OFF_QWH, al_ = su + OFF_QWL;
        const uint32_t bh_ = su + OFF_K + s * 32768, bl_ = bh_ + 16384;
#pragma unroll
        for (int kk = 0; kk < 4; kk++) {
            const int seg = kk * 32 + (lane >> 4) * 16;
            uint32_t afh[2][4], afl[2][4], bfh[8][2], bfl[8][2];
#pragma unroll
            for (int mt = 0; mt < 2; mt++) {
                int sw = SWZ128((wm * 32 + mt * 16 + (lane & 15)) * 128 + seg);
                ldm_x4(afh[mt], ah_ + sw);
                ldm_x4(afl[mt], al_ + sw);
            }
#pragma unroll
            for (int p = 0; p < 4; p++) {
                int sw = SWZ128((wn * 64 + p * 16 + (lane & 15)) * 128 + seg);
                uint32_t r[4];
                ldm_x4(r, bh_ + sw);
                bfh[2 * p][0] = r[0]; bfh[2 * p][1] = r[2];
                bfh[2 * p + 1][0] = r[1]; bfh[2 * p + 1][1] = r[3];
                ldm_x4(r, bl_ + sw);
                bfl[2 * p][0] = r[0]; bfl[2 * p][1] = r[2];
                bfl[2 * p + 1][0] = r[1]; bfl[2 * p + 1][1] = r[3];
            }
#pragma unroll
            for (int mt = 0; mt < 2; mt++)
#pragma unroll
                for (int nt = 0; nt < 8; nt++)
                    mma16816(accS[mt][nt], afh[mt], bfh[nt]);
#pragma unroll
            for (int mt = 0; mt < 2; mt++)
#pragma unroll
                for (int nt = 0; nt < 8; nt++)
                    mma16816(accS[mt][nt], afl[mt], bfh[nt]);
#pragma unroll
            for (int mt = 0; mt < 2; mt++)
#pragma unroll
                for (int nt = 0; nt < 8; nt++)
                    mma16816(accS[mt][nt], afh[mt], bfl[nt]);
        }

#pragma unroll
        for (int mt = 0; mt < 2; mt++)
#pragma unroll
            for (int hf = 0; hf < 2; hf++) {
                int row_l = wm * 32 + mt * 16 + (lane >> 2) + hf * 8;
                int gi = i0 + row_l;
                const float* bdrow = bdb + (size_t)gi * 1024 + (1023 - gi) + j0;
#pragma unroll
                for (int nt = 0; nt < 8; nt++)
#pragma unroll
                    for (int e = 0; e < 2; e++) {
                        int col = wn * 64 + nt * 8 + (lane & 3) * 2 + e;
                        int gj = j0 + col;
                        float v = (gj <= gi) ? (accS[mt][nt][hf * 2 + e] + bdrow[col]) : NEGINF;
                        accS[mt][nt][hf * 2 + e] = v;
                    }
            }

        float m_new[4], alpha[4];
#pragma unroll
        for (int mt = 0; mt < 2; mt++)
#pragma unroll
            for (int hf = 0; hf < 2; hf++) {
                float mx = NEGINF;
#pragma unroll
                for (int nt = 0; nt < 8; nt++)
                    mx = fmaxf(mx, fmaxf(accS[mt][nt][hf * 2], accS[mt][nt][hf * 2 + 1]));
                mx = fmaxf(mx, __shfl_xor_sync(0xffffffffu, mx, 1));
                mx = fmaxf(mx, __shfl_xor_sync(0xffffffffu, mx, 2));
                if ((lane & 3) == 0) redA[wn * 128 + wm * 32 + mt * 16 + (lane >> 2) + hf * 8] = mx;
                m_new[mt * 2 + hf] = mx;
            }
        __syncthreads();
#pragma unroll
        for (int mt = 0; mt < 2; mt++)
#pragma unroll
            for (int hf = 0; hf < 2; hf++) {
                int row_l = wm * 32 + mt * 16 + (lane >> 2) + hf * 8;
                int idx = mt * 2 + hf;
                float comb = fmaxf(redA[row_l], redA[128 + row_l]);
                float mn = fmaxf(m_old[idx], comb);
                alpha[idx] = __expf(m_old[idx] - mn);
                m_new[idx] = mn;
                m_old[idx] = mn;
            }

#pragma unroll
        for (int mt = 0; mt < 2; mt++)
#pragma unroll
            for (int hf = 0; hf < 2; hf++) {
                int idx = mt * 2 + hf;
                float ssum = 0.f;
#pragma unroll
                for (int nt = 0; nt < 8; nt++)
#pragma unroll
                    for (int e = 0; e < 2; e++) {
                        float p = __expf(accS[mt][nt][hf * 2 + e] - m_new[idx]);
                        accS[mt][nt][hf * 2 + e] = p;
                        ssum += p;
                    }
                ssum += __shfl_xor_sync(0xffffffffu, ssum, 1);
                ssum += __shfl_xor_sync(0xffffffffu, ssum, 2);
                if ((lane & 3) == 0) redB[wn * 128 + wm * 32 + mt * 16 + (lane >> 2) + hf * 8] = ssum;
            }
        __syncthreads();
#pragma unroll
        for (int mt = 0; mt < 2; mt++)
#pragma unroll
            for (int hf = 0; hf < 2; hf++) {
                int row_l = wm * 32 + mt * 16 + (lane >> 2) + hf * 8;
                int idx = mt * 2 + hf;
                l_run[idx] = l_run[idx] * alpha[idx] + redB[row_l] + redB[128 + row_l];
            }

#pragma unroll
        for (int mt = 0; mt < 2; mt++)
#pragma unroll
            for (int nt = 0; nt < 4; nt++)
#pragma unroll
                for (int u = 0; u < 4; u++) acc_o[mt][nt][u] *= alpha[mt * 2 + (u >> 1)];

#pragma unroll
        for (int mt = 0; mt < 2; mt++)
#pragma unroll
            for (int hf = 0; hf < 2; hf++) {
                int row_l = wm * 32 + mt * 16 + (lane >> 2) + hf * 8;
#pragma unroll
                for (int nt = 0; nt < 8; nt++) {
                    float v0 = accS[mt][nt][hf * 2], v1 = accS[mt][nt][hf * 2 + 1];
                    __nv_bfloat16 h0, l0, h1, l1;
                    split2(v0, h0, l0);
                    split2(v1, h1, l1);
                    uint32_t off = SWZ128(row_l * 128 + (nt * 8 + (lane & 3) * 2) * 2);
                    *(__nv_bfloat162*)(smem + OFF_PH + wn * 16384 + off) = __nv_bfloat162(h0, h1);
                    *(__nv_bfloat162*)(smem + OFF_PL + wn * 16384 + off) = __nv_bfloat162(l0, l1);
                }
            }
        if (more) cp_wait<1>(); else cp_wait<0>();
        __syncthreads();

#pragma unroll
        for (int kk = 0; kk < 8; kk++) {
            const int ch = kk >> 2;
            const int seg = (kk & 3) * 32 + (lane >> 4) * 16;
            uint32_t pah[2][4], pal[2][4], vbh[4][2], vbl[4][2];
#pragma unroll
            for (int mt = 0; mt < 2; mt++) {
                int sw = SWZ128((wm * 32 + mt * 16 + (lane & 15)) * 128 + seg);
                ldm_x4(pah[mt], su + OFF_PH + ch * 16384 + sw);
                ldm_x4(pal[mt], su + OFF_PL + ch * 16384 + sw);
            }
#pragma unroll
            for (int p = 0; p < 2; p++) {
                int sw = SWZ128((wn * 32 + p * 16 + (lane & 15)) * 128 + seg);
                uint32_t r[4];
                ldm_x4(r, su + OFF_VH + ch * 8192 + sw);
                vbh[2 * p][0] = r[0]; vbh[2 * p][1] = r[2];
                vbh[2 * p + 1][0] = r[1]; vbh[2 * p + 1][1] = r[3];
                ldm_x4(r, su + OFF_VL + ch * 8192 + sw);
                vbl[2 * p][0] = r[0]; vbl[2 * p][1] = r[2];
                vbl[2 * p + 1][0] = r[1]; vbl[2 * p + 1][1] = r[3];
            }
#pragma unroll
            for (int mt = 0; mt < 2; mt++)
#pragma unroll
                for (int nt = 0; nt < 4; nt++)
                    mma16816(acc_o[mt][nt], pah[mt], vbh[nt]);
#pragma unroll
            for (int mt = 0; mt < 2; mt++)
#pragma unroll
                for (int nt = 0; nt < 4; nt++)
                    mma16816(acc_o[mt][nt], pal[mt], vbh[nt]);
#pragma unroll
            for (int mt = 0; mt < 2; mt++)
#pragma unroll
                for (int nt = 0; nt < 4; nt++)
                    mma16816(acc_o[mt][nt], pah[mt], vbl[nt]);
        }
        __syncthreads();
    }

    const int b = bn >> 4, n = bn & 15;
    float inv[4];
#pragma unroll
    for (int i = 0; i < 4; i++) inv[i] = 1.f / l_run[i];
#pragma unroll
    for (int mt = 0; mt < 2; mt++)
#pragma unroll
        for (int nt = 0; nt < 4; nt++)
#pragma unroll
            for (int hf = 0; hf < 2; hf++) {
                int row_l = wm * 32 + mt * 16 + (lane >> 2) + hf * 8;
                int gi = i0 + row_l;
                int d0 = wn * 32 + nt * 8 + (lane & 3) * 2;
                float v0 = acc_o[mt][nt][hf * 2] * inv[mt * 2 + hf];
                float v1 = acc_o[mt][nt][hf * 2 + 1] * inv[mt * 2 + hf];
                size_t orow = (size_t)(gi * 4 + b) * 2048 + n * 64 + d0;
                __nv_bfloat16 h0, l0, h1, l1;
                split2(v0, h0, l0);
                split2(v1, h1, l1);
                *(__nv_bfloat162*)&g_vecbf[orow] = __nv_bfloat162(h0, h1);
                *(__nv_bfloat162*)&g_vecbf[orow + 1024] = __nv_bfloat162(l0, l1);
            }
}

// ---------------- split / transpose / pack kernels ----------------
__global__ void split_kernel(const float* __restrict__ X, __nv_bfloat16* __restrict__ Y, int cols)
{
    int idx = blockIdx.x * 256 + threadIdx.x;
    int row = idx / cols, col = idx - row * cols;
    __nv_bfloat16 h, l;
    split2(X[idx], h, l);
    Y[(size_t)row * 2 * cols + col] = h;
    Y[(size_t)row * 2 * cols + cols + col] = l;
}

__global__ __launch_bounds__(256) void tsplit_kernel(const float* __restrict__ X,
                                                     __nv_bfloat16* __restrict__ Y, int N, int K)
{
    __shared__ float sm[64][65];
    int k0 = blockIdx.x * 64, n0 = blockIdx.y * 64;
    int tid = threadIdx.x;
    for (int e = tid; e < 4096; e += 256) {
        int r = e >> 6, c = e & 63;
        sm[c][r] = X[(size_t)(k0 + r) * N + n0 + c];
    }
    __syncthreads();
    for (int e = tid; e < 4096; e += 256) {
        int r = e >> 6, c = e & 63;
        __nv_bfloat16 h, l;
        split2(sm[r][c], h, l);
        Y[(size_t)(n0 + r) * 2 * K + k0 + c] = h;
        Y[(size_t)(n0 + r) * 2 * K + K + k0 + c] = l;
    }
}

__global__ __launch_bounds__(256) void pack_vt_kernel()
{
    __shared__ float sm[64][65];
    int bn = blockIdx.y, b = bn >> 4, n = bn & 15;
    int j0 = blockIdx.x * 64;
    int tid = threadIdx.x;
    for (int e = tid; e < 4096; e += 256) {
        int jj = e >> 6, d = e & 63;
        sm[d][jj] = g_heads[(size_t)((j0 + jj) * 4 + b) * 3072 + 2048 + n * 64 + d];
    }
    __syncthreads();
    for (int e = tid; e < 4096; e += 256) {
        int d = e >> 6, jj = e & 63;
        __nv_bfloat16 h, l;
        split2(sm[d][jj], h, l);
        g_vtbf[((size_t)bn * 64 + d) * 2048 + j0 + jj] = h;
        g_vtbf[((size_t)bn * 64 + d) * 2048 + 1024 + j0 + jj] = l;
    }
}

// ---------------- residual + layernorm ----------------
__global__ __launch_bounds__(256) void ln_kernel(
    const float* __restrict__ w, const float* __restrict__ gamma,
    const float* __restrict__ beta, float* __restrict__ out)
{
    int row = blockIdx.x;
    const float* wr = w + (size_t)row * DM;
    const float* ar = g_attn + (size_t)row * DM;
    int tid = threadIdx.x;

    float x[4];
    float s = 0.f, s2 = 0.f;
#pragma unroll
    for (int u = 0; u < 4; u++) {
        int c = tid + u * 256;
        x[u] = wr[c] + ar[c];
        s += x[u];
        s2 += x[u] * x[u];
    }
    __shared__ float rs[256], rs2[256];
    rs[tid] = s; rs2[tid] = s2;
    __syncthreads();
    for (int t = 128; t > 0; t >>= 1) {
        if (tid < t) { rs[tid] += rs[tid + t]; rs2[tid] += rs2[tid + t]; }
        __syncthreads();
    }
    float mu = rs[0] * (1.f / DM);
    float var = rs2[0] * (1.f / DM) - mu * mu;
    float rstd = rsqrtf(var + 1e-5f);
#pragma unroll
    for (int u = 0; u < 4; u++) {
        int c = tid + u * 256;
        out[(size_t)row * DM + c] = (x[u] - mu) * rstd * gamma[c] + beta[c];
    }
}

// ---------------- launch ----------------
extern "C" void kernel_launch(void* const* d_in, const int* in_sizes, int n_in,
                              void* d_out, int out_size)
{
    const float* w     = (const float*)d_in[0];
    const float* r     = (const float*)d_in[1];
    const float* rwb   = (const float*)d_in[2];
    const float* rrb   = (const float*)d_in[3];
    const float* W_qkv = (const float*)d_in[5];
    const float* W_r   = (const float*)d_in[6];
    const float* W_o   = (const float*)d_in[7];
    const float* gamma = (const float*)d_in[8];
    const float* beta  = (const float*)d_in[9];
    float* out = (float*)d_out;

    float *p_BD, *p_attn;
    __nv_bfloat16 *p_wbf, *p_rbf, *p_qkvt, *p_wrt, *p_wot;
    __nv_bfloat16 *p_qrbf, *p_rkbf, *p_vecbf;
    cudaGetSymbolAddress((void**)&p_BD, g_BD);
    cudaGetSymbolAddress((void**)&p_attn, g_attn);
    cudaGetSymbolAddress((void**)&p_wbf, g_wbf);
    cudaGetSymbolAddress((void**)&p_rbf, g_rbf);
    cudaGetSymbolAddress((void**)&p_qkvt, g_qkvt);
    cudaGetSymbolAddress((void**)&p_wrt, g_wrt);
    cudaGetSymbolAddress((void**)&p_wot, g_wot);
    cudaGetSymbolAddress((void**)&p_qrbf, g_qrbf);
    cudaGetSymbolAddress((void**)&p_rkbf, g_rkbf);
    cudaGetSymbolAddress((void**)&p_vecbf, g_vecbf);

    cudaFuncSetAttribute(mma_gemm2, cudaFuncAttributeMaxDynamicSharedMemorySize, 131072);
    cudaFuncSetAttribute(flash_kernel, cudaFuncAttributeMaxDynamicSharedMemorySize, 198656);

    const int FULLMASK = 0x7FFFFFFF;
    constexpr int SM128 = 131072;

    split_kernel<<<4096 * 1024 / 256, 256>>>(w, p_wbf, 1024);                 // 0
    tsplit_kernel<<<dim3(16, 48), 256>>>(W_qkv, p_qkvt, 3072, 1024);          // 1

    // heads GEMM with fused pack (q->qw/qr, k->kbf, v->g_heads)
    mma_gemm2<<<dim3(24, 32, 1), 256, SM128>>>(                               // 2
        p_wbf, p_qkvt, nullptr, 1024, 2048, 2048, 0, 0, 0, 0, 0, FULLMASK, 2, rwb, rrb);

    split_kernel<<<1024 * 1024 / 256, 256>>>(r, p_rbf, 1024);                 // 3
    tsplit_kernel<<<dim3(16, 16), 256>>>(W_r, p_wrt, 1024, 1024);             // 4

    // r_k GEMM with fused rk split pack
    mma_gemm2<<<dim3(8, 8, 1), 256, SM128>>>(                                 // 5
        p_rbf, p_wrt, nullptr, 1024, 2048, 2048, 0, 0, 0, 0, 0, FULLMASK, 3, nullptr, nullptr);

    pack_vt_kernel<<<dim3(16, 64), 256>>>();                                  // 6

    // BDrel = qr @ rk^T (anti-tri tiles, B batch = head), pre-scaled 0.125
    mma_gemm2<<<dim3(36, 1, BN_TOT), 256, SM128>>>(                           // 7
        p_qrbf, p_rkbf, p_BD, 64, 128, 128, 1024,
        (long long)QLEN * 128, (long long)QLEN * 128, (long long)QLEN * QLEN,
        2, 15, 0, nullptr, nullptr);

    // fused AC + BD + softmax + PV
    flash_kernel<<<dim3(8, 1, BN_TOT), 256, 198656>>>();                      // 8

    tsplit_kernel<<<dim3(16, 16), 256>>>(W_o, p_wot, 1024, 1024);             // 9

    mma_gemm2<<<dim3(8, 32, 1), 256, SM128>>>(                                // 10: attn
        p_vecbf, p_wot, p_attn, 1024, 2048, 2048, 1024, 0, 0, 0, 0, FULLMASK, 0, nullptr, nullptr);

    ln_kernel<<<4096, 256>>>(w, gamma, beta, out);                            // 11
}